// round 13
// baseline (speedup 1.0000x reference)
#include <cuda_runtime.h>
#include <cuda_bf16.h>
#include <float.h>
#include <math.h>
#include <stdint.h>

// Problem constants
#define BC   128
#define PP   1024
#define NPTS (BC*PP)   // 131072
#define KNN  4
#define KP3  288       // K padded to 288 (9 chunks of 32); N padded to 272
#define NP2  272

typedef unsigned long long ull;

// ---------------------------------------------------------------------------
// Scratch (device globals; no allocation allowed)
__device__ float          g_sq  [NPTS];             // per-point squared norms
__device__ __nv_bfloat16  g_fa_h[NPTS * 128];       // bf16-hi concat feats, fragment-permuted
__device__ __nv_bfloat16  g_fa_l[NPTS * 128];
__device__ __nv_bfloat16  g_xa_h[NPTS * KP3];       // h1 split, fragment-permuted
__device__ __nv_bfloat16  g_xa_l[NPTS * KP3];
__device__ __nv_bfloat16  g_ya_h[NPTS * KP3];       // h2 split, fragment-permuted
__device__ __nv_bfloat16  g_ya_l[NPTS * KP3];
__device__ __nv_bfloat16  g_w_h [3][NP2 * KP3];     // transposed split final-MLP weights
__device__ __nv_bfloat16  g_w_l [3][NP2 * KP3];
__device__ __nv_bfloat16  g_e1h [2][64 * 64];       // edge conv layer1 eff-weights [C][64]
__device__ __nv_bfloat16  g_e1l [2][64 * 64];
__device__ __nv_bfloat16  g_e2h [2][64 * 64];       // edge conv layer2 weights [C][C]
__device__ __nv_bfloat16  g_e2l [2][64 * 64];
__device__ int            g_knn [NPTS * KNN];

// ---------------------------------------------------------------------------
// Fragment-permuted element offset: within each 16-k block, granule
// ((k>>1)&3)^(r&3) holds elements (2q2, 2q2+1, 2q2+8, 2q2+9).
__device__ __forceinline__ long permoff(int r, int k, int stride) {
    int blk = k >> 4;
    int q2  = (k >> 1) & 3;
    int hi  = (k >> 3) & 1;
    int gr  = q2 ^ (r & 3);
    return (long)r * stride + blk * 16 + gr * 4 + hi * 2 + (k & 1);
}

// ---------------------------------------------------------------------------
__device__ __forceinline__ void bsplit(float v, __nv_bfloat16& h, __nv_bfloat16& l) {
    h = __float2bfloat16(v);
    l = __float2bfloat16(v - __bfloat162float(h));
}
__device__ __forceinline__ uint32_t packbf(float lo, float hi) {
    __nv_bfloat16 a = __float2bfloat16(lo), b = __float2bfloat16(hi);
    return ((uint32_t)__bfloat16_as_ushort(b) << 16) | __bfloat16_as_ushort(a);
}

// bf16 HMMA m16n8k16
__device__ __forceinline__ void mma16816(float* c, const uint32_t* a,
                                         uint32_t b0, uint32_t b1) {
    asm volatile(
        "mma.sync.aligned.m16n8k16.row.col.f32.bf16.bf16.f32 "
        "{%0,%1,%2,%3}, {%4,%5,%6,%7}, {%8,%9}, {%0,%1,%2,%3};"
        : "+f"(c[0]), "+f"(c[1]), "+f"(c[2]), "+f"(c[3])
        : "r"(a[0]), "r"(a[1]), "r"(a[2]), "r"(a[3]), "r"(b0), "r"(b1));
}

__device__ __forceinline__ uint32_t smem_u32(const void* p) {
    uint32_t a;
    asm("{ .reg .u64 t; cvta.to.shared.u64 t, %1; cvt.u32.u64 %0, t; }"
        : "=r"(a) : "l"(p));
    return a;
}
__device__ __forceinline__ uint2 lds64(uint32_t addr) {
    uint2 v;
    asm volatile("ld.shared.v2.u32 {%0,%1}, [%2];" : "=r"(v.x), "=r"(v.y) : "r"(addr));
    return v;
}
__device__ __forceinline__ void cp16(uint32_t saddr, const void* gaddr) {
    asm volatile("cp.async.cg.shared.global [%0], [%1], 16;" :: "r"(saddr), "l"(gaddr));
}
#define CP_COMMIT() asm volatile("cp.async.commit_group;" ::: "memory")
#define CP_WAIT1()  asm volatile("cp.async.wait_group 1;" ::: "memory")
#define CP_WAIT0()  asm volatile("cp.async.wait_group 0;" ::: "memory")

// top-4 insertion ladder (strict <, earliest-seen wins ties)
__device__ __forceinline__ void lad4(float* bs, int* bi, float s, int id) {
    if (s < bs[3]) {
        if (s < bs[2]) {
            bs[3] = bs[2]; bi[3] = bi[2];
            if (s < bs[1]) {
                bs[2] = bs[1]; bi[2] = bi[1];
                if (s < bs[0]) { bs[1] = bs[0]; bi[1] = bi[0]; bs[0] = s; bi[0] = id; }
                else           { bs[1] = s; bi[1] = id; }
            } else { bs[2] = s; bi[2] = id; }
        } else { bs[3] = s; bi[3] = id; }
    }
}

// ---------------------------------------------------------------------------
// kNN for D=1 (exact fp32; input feature space)
__global__ void knn1_kernel(const float* __restrict__ feat, int* __restrict__ kn) {
    const int NT = 256;
    __shared__ float s[NT];
    int cloud = blockIdx.x / (PP / 256);
    int tile  = blockIdx.x % (PP / 256);
    int gi    = cloud * PP + tile * 256 + threadIdx.x;

    float f0 = feat[gi];
    float bd[4] = { FLT_MAX, FLT_MAX, FLT_MAX, FLT_MAX };
    int   bi[4] = { 0, 0, 0, 0 };

    for (int j0 = 0; j0 < PP; j0 += NT) {
        __syncthreads();
        s[threadIdx.x] = feat[cloud * PP + j0 + threadIdx.x];
        __syncthreads();
        for (int jj = 0; jj < NT; jj++) {
            float df = f0 - s[jj];
            lad4(bd, bi, df * df, cloud * PP + j0 + jj);
        }
    }
    kn[gi*4+0] = bi[0]; kn[gi*4+1] = bi[1]; kn[gi*4+2] = bi[2]; kn[gi*4+3] = bi[3];
}

// ---------------------------------------------------------------------------
// Squared norms from the bf16 hi/lo split.
__global__ void sqnorm_kernel(const __nv_bfloat16* __restrict__ Fh,
                              const __nv_bfloat16* __restrict__ Fl,
                              int kb0, float* __restrict__ sq) {
    int p = blockIdx.x * 256 + threadIdx.x;
    if (p >= NPTS) return;
    const __nv_bfloat16* ph = Fh + (long)p * 128 + kb0 * 16;
    const __nv_bfloat16* pl = Fl + (long)p * 128 + kb0 * 16;
    float s = 0.f;
#pragma unroll
    for (int i = 0; i < 32; i++) {
        float v = __bfloat162float(ph[i]) + __bfloat162float(pl[i]);
        s = fmaf(v, v, s);
    }
    sq[p] = s;
}

// ---------------------------------------------------------------------------
// Fused HMMA kNN (D=32): per CTA 64 queries x 1024 candidates of one cloud.
__global__ void __launch_bounds__(256, 2)
knn_mma(const __nv_bfloat16* __restrict__ Fh, const __nv_bfloat16* __restrict__ Fl,
        int kb0, const float* __restrict__ sq, int* __restrict__ kn) {
    extern __shared__ char smem[];
    const int OFF_A  = 0;
    const int OFF_B  = 12288;
    const int OFF_SQ = 61440;
    const int OFF_MG = 12288;
    const int ATERM  = 64 * 96;
    const int BTERM  = 256 * 96;

    uint32_t sb = smem_u32(smem);
    int tid = threadIdx.x, wid = tid >> 5, lane = tid & 31;
    int cloud = blockIdx.x >> 4;
    int qbase = (blockIdx.x & 15) * 64;
    int gq    = cloud * PP + qbase;
    int gc0   = cloud * PP;
    int wm = wid >> 2, wn = wid & 3;
    int g  = lane >> 2, qi = lane & 3, q = qi * 2;

    for (int idx = tid; idx < 512; idx += 256) {
        int term = idx >> 8, rem = idx & 255;
        int r = rem >> 2, c = rem & 3;
        const __nv_bfloat16* src =
            (term ? Fl : Fh) + (long)(gq + r) * 128 + (kb0 + (c >> 1)) * 16 + (c & 1) * 8;
        cp16(sb + OFF_A + term * ATERM + r * 96 + c * 16, src);
    }
    CP_COMMIT();

    float bs[4][4]; int bi[4][4];
#pragma unroll
    for (int a = 0; a < 4; a++)
#pragma unroll
        for (int b = 0; b < 4; b++) { bs[a][b] = FLT_MAX; bi[a][b] = 0; }

    const uint32_t frOff = (uint32_t)((qi ^ (g & 3)) << 3);

    for (int nc = 0; nc < 4; nc++) {
        int cb = nc * 256;
        __syncthreads();
        for (int idx = tid; idx < 2048; idx += 256) {
            int term = idx >> 10, rem = idx & 1023;
            int r = rem >> 2, c = rem & 3;
            const __nv_bfloat16* src =
                (term ? Fl : Fh) + (long)(gc0 + cb + r) * 128 + (kb0 + (c >> 1)) * 16 + (c & 1) * 8;
            cp16(sb + OFF_B + term * BTERM + r * 96 + c * 16, src);
        }
        if (tid < 64)
            cp16(sb + OFF_SQ + tid * 16, sq + gc0 + cb + tid * 4);
        CP_COMMIT();
        CP_WAIT0();
        __syncthreads();

        const float* ssq = (const float*)(smem + OFF_SQ);
#pragma unroll
        for (int mt = 0; mt < 2; mt++) {
            float acc[8][4];
#pragma unroll
            for (int nt = 0; nt < 8; nt++)
#pragma unroll
                for (int c = 0; c < 4; c++) acc[nt][c] = 0.0f;

#pragma unroll
            for (int s = 0; s < 2; s++) {
                uint32_t ao = (uint32_t)((wm * 32 + mt * 16 + g) * 96 + s * 32) + frOff;
                uint2 aHlo = lds64(sb + OFF_A + ao);
                uint2 aHhi = lds64(sb + OFF_A + ao + 8 * 96);
                uint2 aLlo = lds64(sb + OFF_A + ATERM + ao);
                uint2 aLhi = lds64(sb + OFF_A + ATERM + ao + 8 * 96);
                uint32_t aH[4] = { aHlo.x, aHhi.x, aHlo.y, aHhi.y };
                uint32_t aL[4] = { aLlo.x, aLhi.x, aLlo.y, aLhi.y };
#pragma unroll
                for (int nt = 0; nt < 8; nt++) {
                    int n = wn * 64 + nt * 8 + g;
                    uint32_t bo = (uint32_t)(n * 96 + s * 32) + frOff;
                    uint2 bh = lds64(sb + OFF_B + bo);
                    uint2 bl = lds64(sb + OFF_B + BTERM + bo);
                    mma16816(acc[nt], aH, bh.x, bh.y);
                    mma16816(acc[nt], aH, bl.x, bl.y);
                    mma16816(acc[nt], aL, bh.x, bh.y);
                }
            }
#pragma unroll
            for (int nt = 0; nt < 8; nt++) {
                int col = wn * 64 + nt * 8 + q;
                float sj0 = ssq[col], sj1 = ssq[col + 1];
#pragma unroll
                for (int h = 0; h < 2; h++) {
                    int li = mt * 2 + h;
                    lad4(bs[li], bi[li], sj0 - 2.0f * acc[nt][h*2+0], cb + col);
                    lad4(bs[li], bi[li], sj1 - 2.0f * acc[nt][h*2+1], cb + col + 1);
                }
            }
        }
    }

    __syncthreads();
    float2* mg = (float2*)(smem + OFF_MG);
    int src = wn * 4 + qi;
#pragma unroll
    for (int mt = 0; mt < 2; mt++)
#pragma unroll
        for (int h = 0; h < 2; h++) {
            int row = wm * 32 + mt * 16 + h * 8 + g;
            int li = mt * 2 + h;
#pragma unroll
            for (int k = 0; k < 4; k++)
                mg[(row * 16 + src) * 4 + k] =
                    make_float2(bs[li][k], __int_as_float(bi[li][k]));
        }
    __syncthreads();
    if (tid < 64) {
        float fs[4] = { FLT_MAX, FLT_MAX, FLT_MAX, FLT_MAX };
        int   fi[4] = { 0, 0, 0, 0 };
        const float2* rowp = mg + tid * 64;
        for (int e = 0; e < 64; e++) {
            float2 p = rowp[(e + tid) & 63];
            lad4(fs, fi, p.x, __float_as_int(p.y));
        }
        int gpt = gq + tid;
#pragma unroll
        for (int k = 0; k < 4; k++) kn[gpt * 4 + k] = gc0 + fi[k];
    }
}

// ---------------------------------------------------------------------------
// Edge conv D=1: warp-per-point (fp32 math), writes permuted bf16 split cols 0..31.
__global__ void edge_conv1_kernel(const float* __restrict__ feat,
                                  const int* __restrict__ kn,
                                  const float* __restrict__ W1, const float* __restrict__ b1,
                                  const float* __restrict__ W2, const float* __restrict__ b2,
                                  __nv_bfloat16* __restrict__ bqh,
                                  __nv_bfloat16* __restrict__ bql) {
    const int C = 32;
    __shared__ float sW1[2 * C];
    __shared__ float sW2[C * C];
    __shared__ float sb1[C], sb2[C];
    __shared__ float sh[8][C];

    int tid = threadIdx.x;
    for (int i = tid; i < 2 * C; i += 256) sW1[i] = W1[i];
    for (int i = tid; i < C * C; i += 256) sW2[i] = W2[i];
    if (tid < C) { sb1[tid] = b1[tid]; sb2[tid] = b2[tid]; }
    __syncthreads();

    int w = tid / 32, lane = tid % 32;
    int pt = blockIdx.x * 8 + w;
    float xi = feat[pt];

    float acc = -FLT_MAX;
#pragma unroll
    for (int k = 0; k < KNN; k++) {
        int j = kn[pt * 4 + k];
        float dj = feat[j] - xi;
        float hv = fmaf(xi, sW1[lane], fmaf(dj, sW1[C + lane], sb1[lane]));
        sh[w][lane] = fmaxf(hv, 0.f);
        __syncwarp();
        float ov = sb2[lane];
#pragma unroll
        for (int t = 0; t < C; t++) ov = fmaf(sh[w][t], sW2[t * C + lane], ov);
        acc = fmaxf(acc, ov);
        __syncwarp();
    }
    __nv_bfloat16 h, l; bsplit(acc, h, l);
    long o = permoff(pt, lane, 128);
    bqh[o] = h;
    bql[o] = l;
}

// ---------------------------------------------------------------------------
// Edge-conv weight prep:
// layer1 effective weights: [xi,xj] form: rows k<32: W1a-W1b, k>=32: W1b.
// stored transposed+split+permuted as [C][64].
__global__ void wedge1_kernel(const float* __restrict__ W1, int C,
                              __nv_bfloat16* __restrict__ th,
                              __nv_bfloat16* __restrict__ tl) {
    int idx = blockIdx.x * 256 + threadIdx.x;
    if (idx >= C * 64) return;
    int n = idx / 64, k = idx % 64;
    float v = (k < 32) ? (W1[k * C + n] - W1[(k + 32) * C + n]) : W1[k * C + n];
    __nv_bfloat16 h, l; bsplit(v, h, l);
    long o = permoff(n, k, 64);
    th[o] = h; tl[o] = l;
}
// layer2 weights transposed+split+permuted as [C][C].
__global__ void wedge2_kernel(const float* __restrict__ W2, int C,
                              __nv_bfloat16* __restrict__ th,
                              __nv_bfloat16* __restrict__ tl) {
    int idx = blockIdx.x * 256 + threadIdx.x;
    if (idx >= C * C) return;
    int n = idx / C, k = idx % C;
    float v = W2[k * C + n];
    __nv_bfloat16 h, l; bsplit(v, h, l);
    long o = permoff(n, k, C);
    th[o] = h; tl[o] = l;
}

// ---------------------------------------------------------------------------
// HMMA edge conv (D=32 -> C): per CTA 128 edge rows (32 points).
// A row = [Xi | Xj] gathered verbatim from the permuted feature buffer
// (granule parity follows SOURCE row; fixed up at fragment-load time).
// Layer2 A-fragments come straight from layer1 accumulators (no smem).
// Weights read as B-fragments directly from global (L1-hot).
template<int C>
__global__ void __launch_bounds__(128, 2)
edge_mma(const __nv_bfloat16* __restrict__ Fh, const __nv_bfloat16* __restrict__ Fl,
         int kb0, const int* __restrict__ kn,
         const __nv_bfloat16* __restrict__ W1h, const __nv_bfloat16* __restrict__ W1l,
         const __nv_bfloat16* __restrict__ W2h, const __nv_bfloat16* __restrict__ W2l,
         const float* __restrict__ b1, const float* __restrict__ b2, int colbase,
         __nv_bfloat16* __restrict__ Oh, __nv_bfloat16* __restrict__ Ol) {
    constexpr int NT  = C / 8;    // n-tiles
    constexpr int KS2 = C / 16;   // layer2 k-steps
    extern __shared__ char smem[];
    const int OFF_J = 0, OFF_B1 = 128, OFF_B2 = 384, OFF_A = 1024;
#define EASLOT(kch, term, row) (OFF_A + (((kch)*2 + (term)) * 128 + (row)) * 96)

    uint32_t sb = smem_u32(smem);
    int tid = threadIdx.x, w = tid >> 5, lane = tid & 31;
    int g = lane >> 2, qi = lane & 3, q = qi * 2;
    int E0 = blockIdx.x * 128;

    // ---- stage A (128 edge rows x [Xi|Xj] x 2 terms) + j parity table ----
    {
        int e = E0 + tid;
        int i = e >> 2;
        int j = kn[e];
        ((unsigned char*)smem)[OFF_J + tid] = (unsigned char)(j & 3);
        const char* pIh = (const char*)(Fh + (long)i * 128) + kb0 * 32;
        const char* pIl = (const char*)(Fl + (long)i * 128) + kb0 * 32;
        const char* pJh = (const char*)(Fh + (long)j * 128) + kb0 * 32;
        const char* pJl = (const char*)(Fl + (long)j * 128) + kb0 * 32;
        uint32_t a00 = sb + EASLOT(0, 0, tid), a01 = sb + EASLOT(0, 1, tid);
        uint32_t a10 = sb + EASLOT(1, 0, tid), a11 = sb + EASLOT(1, 1, tid);
#pragma unroll
        for (int c = 0; c < 4; c++) {
            cp16(a00 + c * 16, pIh + c * 16);
            cp16(a01 + c * 16, pIl + c * 16);
            cp16(a10 + c * 16, pJh + c * 16);
            cp16(a11 + c * 16, pJl + c * 16);
        }
    }
    if (tid < C) {
        ((float*)(smem + OFF_B1))[tid] = b1[tid];
        ((float*)(smem + OFF_B2))[tid] = b2[tid];
    }
    CP_COMMIT();
    CP_WAIT0();
    __syncthreads();

    const float* b1s = (const float*)(smem + OFF_B1);
    const float* b2s = (const float*)(smem + OFF_B2);
    const unsigned char* j3t = (const unsigned char*)(smem + OFF_J);
    const uint32_t frW = (uint32_t)((qi ^ (g & 3)) << 3);

    // ---- layer 1 -> packed H fragments in registers ----
    uint32_t hH[2][NT][2], hL[2][NT][2];
#pragma unroll
    for (int mt = 0; mt < 2; mt++) {
        int tb  = (w * 2 + mt) * 16;
        int rlo = tb + g, rhi = rlo + 8;
        int i3lo = (rlo >> 2) & 3, i3hi = (rhi >> 2) & 3;
        int j3lo = j3t[rlo], j3hi = j3t[rhi];

        float acc1[NT][4];
#pragma unroll
        for (int nt = 0; nt < NT; nt++)
#pragma unroll
            for (int c = 0; c < 4; c++) acc1[nt][c] = 0.0f;

#pragma unroll
        for (int kch = 0; kch < 2; kch++) {
            uint32_t fLo = (uint32_t)((qi ^ (kch ? j3lo : i3lo)) << 3);
            uint32_t fHi = (uint32_t)((qi ^ (kch ? j3hi : i3hi)) << 3);
#pragma unroll
            for (int s = 0; s < 2; s++) {
                uint2 xHlo = lds64(sb + EASLOT(kch, 0, rlo) + s * 32 + fLo);
                uint2 xHhi = lds64(sb + EASLOT(kch, 0, rhi) + s * 32 + fHi);
                uint2 xLlo = lds64(sb + EASLOT(kch, 1, rlo) + s * 32 + fLo);
                uint2 xLhi = lds64(sb + EASLOT(kch, 1, rhi) + s * 32 + fHi);
                uint32_t aH[4] = { xHlo.x, xHhi.x, xHlo.y, xHhi.y };
                uint32_t aL[4] = { xLlo.x, xLhi.x, xLlo.y, xLhi.y };
                int b = kch * 2 + s;
#pragma unroll
                for (int nt = 0; nt < NT; nt++) {
                    int n = nt * 8 + g;
                    uint2 bh = *(const uint2*)((const char*)W1h + n * 128 + b * 32 + frW);
                    uint2 bl = *(const uint2*)((const char*)W1l + n * 128 + b * 32 + frW);
                    mma16816(acc1[nt], aH, bh.x, bh.y);
                    mma16816(acc1[nt], aH, bl.x, bl.y);
                    mma16816(acc1[nt], aL, bh.x, bh.y);
                }
            }
        }
        // relu + b1, split+pack into MMA2 A-fragments (thread-local!)
#pragma unroll
        for (int nt = 0; nt < NT; nt++) {
            int c0 = nt * 8 + q;
            float bb0 = b1s[c0], bb1 = b1s[c0 + 1];
            float v00 = fmaxf(acc1[nt][0] + bb0, 0.f);
            float v01 = fmaxf(acc1[nt][1] + bb1, 0.f);
            float v10 = fmaxf(acc1[nt][2] + bb0, 0.f);
            float v11 = fmaxf(acc1[nt][3] + bb1, 0.f);
            __nv_bfloat16 h0, l0, h1, l1;
            bsplit(v00, h0, l0); bsplit(v01, h1, l1);
            hH[mt][nt][0] = ((uint32_t)__bfloat16_as_ushort(h1) << 16) | __bfloat16_as_ushort(h0);
            hL[mt][nt][0] = ((uint32_t)__bfloat16_as_ushort(l1) << 16) | __bfloat16_as_ushort(l0);
            bsplit(v10, h0, l0); bsplit(v11, h1, l1);
            hH[mt][nt][1] = ((uint32_t)__bfloat16_as_ushort(h1) << 16) | __bfloat16_as_ushort(h0);
            hL[mt][nt][1] = ((uint32_t)__bfloat16_as_ushort(l1) << 16) | __bfloat16_as_ushort(l0);
        }
    }

    // ---- layer 2 ----
    float acc2[2][NT][4];
#pragma unroll
    for (int mt = 0; mt < 2; mt++)
#pragma unroll
        for (int nt = 0; nt < NT; nt++)
#pragma unroll
            for (int c = 0; c < 4; c++) acc2[mt][nt][c] = 0.0f;

#pragma unroll
    for (int mt = 0; mt < 2; mt++) {
#pragma unroll
        for (int s2 = 0; s2 < KS2; s2++) {
            uint32_t aH[4] = { hH[mt][2*s2][0], hH[mt][2*s2][1],
                               hH[mt][2*s2+1][0], hH[mt][2*s2+1][1] };
            uint32_t aL[4] = { hL[mt][2*s2][0], hL[mt][2*s2][1],
                               hL[mt][2*s2+1][0], hL[mt][2*s2+1][1] };
#pragma unroll
            for (int nt = 0; nt < NT; nt++) {
                int n = nt * 8 + g;
                uint2 bh = *(const uint2*)((const char*)W2h + n * (C * 2) + s2 * 32 + frW);
                uint2 bl = *(const uint2*)((const char*)W2l + n * (C * 2) + s2 * 32 + frW);
                mma16816(acc2[mt][nt], aH, bh.x, bh.y);
                mma16816(acc2[mt][nt], aH, bl.x, bl.y);
                mma16816(acc2[mt][nt], aL, bh.x, bh.y);
            }
        }
    }

    // ---- max over the 4 edges of each point (rows 4p..4p+3) + b2, write ----
    const unsigned FULL = 0xffffffffu;
#pragma unroll
    for (int mt = 0; mt < 2; mt++) {
        int tb = (w * 2 + mt) * 16;
#pragma unroll
        for (int nt = 0; nt < NT; nt++) {
            float m0 = acc2[mt][nt][0], m1 = acc2[mt][nt][1];
            float m2 = acc2[mt][nt][2], m3 = acc2[mt][nt][3];
            m0 = fmaxf(m0, __shfl_xor_sync(FULL, m0, 4));
            m0 = fmaxf(m0, __shfl_xor_sync(FULL, m0, 8));
            m1 = fmaxf(m1, __shfl_xor_sync(FULL, m1, 4));
            m1 = fmaxf(m1, __shfl_xor_sync(FULL, m1, 8));
            m2 = fmaxf(m2, __shfl_xor_sync(FULL, m2, 4));
            m2 = fmaxf(m2, __shfl_xor_sync(FULL, m2, 8));
            m3 = fmaxf(m3, __shfl_xor_sync(FULL, m3, 4));
            m3 = fmaxf(m3, __shfl_xor_sync(FULL, m3, 8));
            if ((g & 3) == 0) {
                int c0 = nt * 8 + q;
                float bb0 = b2s[c0], bb1 = b2s[c0 + 1];
                int plo = (E0 + tb + g) >> 2;
                int phi = (E0 + tb + g + 8) >> 2;
                __nv_bfloat16 h0, l0, h1, l1;
                bsplit(m0 + bb0, h0, l0); bsplit(m1 + bb1, h1, l1);
                long o = permoff(plo, colbase + c0, 128);
                *(uint32_t*)(Oh + o) = ((uint32_t)__bfloat16_as_ushort(h1) << 16) | __bfloat16_as_ushort(h0);
                *(uint32_t*)(Ol + o) = ((uint32_t)__bfloat16_as_ushort(l1) << 16) | __bfloat16_as_ushort(l0);
                bsplit(m2 + bb0, h0, l0); bsplit(m3 + bb1, h1, l1);
                long o2 = permoff(phi, colbase + c0, 128);
                *(uint32_t*)(Oh + o2) = ((uint32_t)__bfloat16_as_ushort(h1) << 16) | __bfloat16_as_ushort(h0);
                *(uint32_t*)(Ol + o2) = ((uint32_t)__bfloat16_as_ushort(l1) << 16) | __bfloat16_as_ushort(l0);
            }
        }
    }
#undef EASLOT
}

// ---------------------------------------------------------------------------
// Weight transpose + split to permuted layout: W[K,264] -> [NP2][KP3]
__global__ void wconv_kernel(const float* __restrict__ W, int K,
                             __nv_bfloat16* __restrict__ th,
                             __nv_bfloat16* __restrict__ tl) {
    int idx = blockIdx.x * 256 + threadIdx.x;
    if (idx >= NP2 * KP3) return;
    int n = idx / KP3, k = idx % KP3;
    float v = (n < 264 && k < K) ? W[(long)k * 264 + n] : 0.0f;
    __nv_bfloat16 h, l; bsplit(v, h, l);
    long o = permoff(n, k, KP3);
    th[o] = h; tl[o] = l;
}

// Zero activation K-pad blocks [272,288)
__global__ void padzero_kernel(__nv_bfloat16* a, __nv_bfloat16* b,
                               __nv_bfloat16* c, __nv_bfloat16* d) {
    int row = blockIdx.x * 256 + threadIdx.x;
    if (row >= NPTS) return;
    uint4 z = make_uint4(0, 0, 0, 0);
    long o = (long)row * KP3 + 272;
    *(uint4*)(a + o) = z; *(uint4*)(a + o + 8) = z;
    *(uint4*)(b + o) = z; *(uint4*)(b + o + 8) = z;
    *(uint4*)(c + o) = z; *(uint4*)(c + o + 8) = z;
    *(uint4*)(d + o) = z; *(uint4*)(d + o + 8) = z;
}

// ---------------------------------------------------------------------------
// HMMA bf16-split GEMM, cp.async double-buffered, conflict-free fragment smem.
// EPI 0: permuted bf16-split out. EPI 2: fused 264->2 + log_softmax.
template<int KTOT, int EPI>
__global__ void __launch_bounds__(512, 1)
gemm_mma(const __nv_bfloat16* __restrict__ Ah, const __nv_bfloat16* __restrict__ Al,
         const __nv_bfloat16* __restrict__ Bh, const __nv_bfloat16* __restrict__ Bl,
         const float* __restrict__ bias,
         __nv_bfloat16* __restrict__ Oh, __nv_bfloat16* __restrict__ Ol,
         const float* __restrict__ W4, const float* __restrict__ b4,
         float* __restrict__ Out) {
    extern __shared__ char smem[];
    const int OFF_W4 = 1088, OFF_RED = 3264, OFF_A = 5312, OFF_B = 54464;
    const int ABUF = 24576, ATERM = 12288, BBUF = 52224, BTERM = 26112;

    uint32_t sb = smem_u32(smem);
    int tid = threadIdx.x, wid = tid >> 5, lane = tid & 31;
    int m0 = blockIdx.x * 128;
    int wm = wid & 7, wn = wid >> 3;
    int g  = lane >> 2;
    int qi = lane & 3;
    int q  = qi * 2;

    float* bias_s = (float*)smem;
    if (tid < NP2) bias_s[tid] = (tid < 264) ? bias[tid] : 0.0f;
    if (EPI == 2) {
        float* w4s = (float*)(smem + OFF_W4);
        for (int i = tid; i < 544; i += 512) w4s[i] = (i < 528) ? W4[i] : 0.0f;
    }

    float acc[17][4];
#pragma unroll
    for (int t = 0; t < 17; t++)
#pragma unroll
        for (int c = 0; c < 4; c++) acc[t][c] = 0.0f;

    constexpr int NCH = KTOT / 32;

    auto stage = [&](int buf, int k0) {
#pragma unroll
        for (int l = 0; l < 2; l++) {
            int idx = tid + l * 512;
            int term = idx >> 9, rem = idx & 511;
            int r = rem >> 2, c = rem & 3;
            const __nv_bfloat16* src =
                (term ? Al : Ah) + (long)(m0 + r) * KTOT + k0 + c * 8;
            cp16(sb + OFF_A + buf * ABUF + term * ATERM + r * 96 + c * 16, src);
        }
        for (int idx = tid; idx < 2176; idx += 512) {
            int term = idx >= 1088;
            int rem  = idx - term * 1088;
            int n = rem >> 2, c = rem & 3;
            const __nv_bfloat16* src =
                (term ? Bl : Bh) + (long)n * KP3 + k0 + c * 8;
            cp16(sb + OFF_B + buf * BBUF + term * BTERM + n * 96 + c * 16, src);
        }
    };

    stage(0, 0);
    CP_COMMIT();

    const uint32_t frOff = (uint32_t)((qi ^ (g & 3)) << 3);
    const int rb = wm * 16 + g;

    for (int ch = 0; ch < NCH; ch++) {
        if (ch + 1 < NCH) {
            stage((ch + 1) & 1, (ch + 1) * 32);
            CP_COMMIT();
            CP_WAIT1();
        } else {
            CP_WAIT0();
        }
        __syncthreads();
        int buf = ch & 1;
        uint32_t aBase = sb + OFF_A + buf * ABUF;
        uint32_t bBase = sb + OFF_B + buf * BBUF;

#pragma unroll
        for (int s = 0; s < 2; s++) {
            uint32_t ao = (uint32_t)(rb * 96 + s * 32) + frOff;
            uint2 aHlo = lds64(aBase + ao);
            uint2 aHhi = lds64(aBase + ao + 8 * 96);
            uint2 aLlo = lds64(aBase + ATERM + ao);
            uint2 aLhi = lds64(aBase + ATERM + ao + 8 * 96);
            uint32_t aH[4] = { aHlo.x, aHhi.x, aHlo.y, aHhi.y };
            uint32_t aL[4] = { aLlo.x, aLhi.x, aLlo.y, aLhi.y };
#pragma unroll
            for (int t = 0; t < 17; t++) {
                int n = wn * 136 + t * 8 + g;
                uint32_t bo = (uint32_t)(n * 96 + s * 32) + frOff;
                uint2 bh = lds64(bBase + bo);
                uint2 bl = lds64(bBase + BTERM + bo);
                mma16816(acc[t], aH, bh.x, bh.y);
                mma16816(acc[t], aH, bl.x, bl.y);
                mma16816(acc[t], aL, bh.x, bh.y);
            }
        }
        __syncthreads();
    }

    int row0 = m0 + wm * 16 + g;
    if (EPI == 0) {
#pragma unroll
        for (int t = 0; t < 17; t++) {
            int c0 = wn * 136 + t * 8 + q;
            float b0 = bias_s[c0], b1v = bias_s[c0 + 1];
            float v00 = fmaxf(acc[t][0] + b0, 0.f);
            float v01 = fmaxf(acc[t][1] + b1v, 0.f);
            float v10 = fmaxf(acc[t][2] + b0, 0.f);
            float v11 = fmaxf(acc[t][3] + b1v, 0.f);
            __nv_bfloat16 h0, l0, h1, l1;
            bsplit(v00, h0, l0); bsplit(v01, h1, l1);
            uint32_t ph = ((uint32_t)__bfloat16_as_ushort(h1) << 16) | __bfloat16_as_ushort(h0);
            uint32_t pl = ((uint32_t)__bfloat16_as_ushort(l1) << 16) | __bfloat16_as_ushort(l0);
            long o = permoff(row0, c0, KP3);
            *(uint32_t*)(Oh + o) = ph;
            *(uint32_t*)(Ol + o) = pl;
            bsplit(v10, h0, l0); bsplit(v11, h1, l1);
            ph = ((uint32_t)__bfloat16_as_ushort(h1) << 16) | __bfloat16_as_ushort(h0);
            pl = ((uint32_t)__bfloat16_as_ushort(l1) << 16) | __bfloat16_as_ushort(l0);
            long o2 = permoff(row0 + 8, c0, KP3);
            *(uint32_t*)(Oh + o2) = ph;
            *(uint32_t*)(Ol + o2) = pl;
        }
    } else {
        const float* w4s = (const float*)(smem + OFF_W4);
        float p00 = 0.f, p01 = 0.f, p10 = 0.f, p11 = 0.f;
#pragma unroll
        for (int t = 0; t < 17; t++) {
            int c0 = wn * 136 + t * 8 + q;
            float b0 = bias_s[c0], b1v = bias_s[c0 + 1];
            float v00 = fmaxf(acc[t][0] + b0, 0.f);
            float v01 = fmaxf(acc[t][1] + b1v, 0.f);
            float v10 = fmaxf(acc[t][2] + b0, 0.f);
            float v11 = fmaxf(acc[t][3] + b1v, 0.f);
            float w00 = w4s[c0 * 2],       w01 = w4s[c0 * 2 + 1];
            float w10 = w4s[(c0 + 1) * 2], w11 = w4s[(c0 + 1) * 2 + 1];
            p00 = fmaf(v00, w00, fmaf(v01, w10, p00));
            p01 = fmaf(v00, w01, fmaf(v01, w11, p01));
            p10 = fmaf(v10, w00, fmaf(v11, w10, p10));
            p11 = fmaf(v10, w01, fmaf(v11, w11, p11));
        }
#pragma unroll
        for (int o = 1; o < 4; o <<= 1) {
            p00 += __shfl_xor_sync(0xFFFFFFFFu, p00, o);
            p01 += __shfl_xor_sync(0xFFFFFFFFu, p01, o);
            p10 += __shfl_xor_sync(0xFFFFFFFFu, p10, o);
            p11 += __shfl_xor_sync(0xFFFFFFFFu, p11, o);
        }
        float* red = (float*)(smem + OFF_RED);
        if (qi == 0) {
            int r = wm * 16 + g;
            red[(wn * 128 + r) * 2 + 0]     = p00;
            red[(wn * 128 + r) * 2 + 1]     = p01;
            red[(wn * 128 + r + 8) * 2 + 0] = p10;
            red[(wn * 128 + r + 8) * 2 + 1] = p11;
        }
        __syncthreads();
        if (tid < 128) {
            float o0 = red[tid * 2 + 0] + red[(128 + tid) * 2 + 0] + b4[0];
            float o1 = red[tid * 2 + 1] + red[(128 + tid) * 2 + 1] + b4[1];
            float m = fmaxf(o0, o1);
            float lse = m + logf(expf(o0 - m) + expf(o1 - m));
            Out[(long)(m0 + tid) * 2 + 0] = o0 - lse;
            Out[(long)(m0 + tid) * 2 + 1] = o1 - lse;
        }
    }
}

// ---------------------------------------------------------------------------
extern "C" void kernel_launch(void* const* d_in, const int* in_sizes, int n_in,
                              void* d_out, int out_size) {
    const float* x    = (const float*)d_in[0];
    const float* c1W1 = (const float*)d_in[2];
    const float* c1b1 = (const float*)d_in[3];
    const float* c1W2 = (const float*)d_in[4];
    const float* c1b2 = (const float*)d_in[5];
    const float* c2W1 = (const float*)d_in[6];
    const float* c2b1 = (const float*)d_in[7];
    const float* c2W2 = (const float*)d_in[8];
    const float* c2b2 = (const float*)d_in[9];
    const float* c3W1 = (const float*)d_in[10];
    const float* c3b1 = (const float*)d_in[11];
    const float* c3W2 = (const float*)d_in[12];
    const float* c3b2 = (const float*)d_in[13];
    const float* mW1  = (const float*)d_in[14];
    const float* mb1  = (const float*)d_in[15];
    const float* mW2  = (const float*)d_in[16];
    const float* mb2  = (const float*)d_in[17];
    const float* mW3  = (const float*)d_in[18];
    const float* mb3  = (const float*)d_in[19];
    const float* mW4  = (const float*)d_in[20];
    const float* mb4  = (const float*)d_in[21];
    float* out = (float*)d_out;

    float* sq; int* knn;
    __nv_bfloat16 *fah, *fal, *xah, *xal, *yah, *yal, *wh, *wl;
    __nv_bfloat16 *e1h, *e1l, *e2h, *e2l;
    cudaGetSymbolAddress((void**)&sq,  g_sq);
    cudaGetSymbolAddress((void**)&knn, g_knn);
    cudaGetSymbolAddress((void**)&fah, g_fa_h);
    cudaGetSymbolAddress((void**)&fal, g_fa_l);
    cudaGetSymbolAddress((void**)&xah, g_xa_h);
    cudaGetSymbolAddress((void**)&xal, g_xa_l);
    cudaGetSymbolAddress((void**)&yah, g_ya_h);
    cudaGetSymbolAddress((void**)&yal, g_ya_l);
    cudaGetSymbolAddress((void**)&wh,  g_w_h);
    cudaGetSymbolAddress((void**)&wl,  g_w_l);
    cudaGetSymbolAddress((void**)&e1h, g_e1h);
    cudaGetSymbolAddress((void**)&e1l, g_e1l);
    cudaGetSymbolAddress((void**)&e2h, g_e2h);
    cudaGetSymbolAddress((void**)&e2l, g_e2l);

    const int SMEM_GEMM = 158912;
    const int SMEM_KNN  = 62464;
    const int SMEM_EDGE = 50176;
    cudaFuncSetAttribute(gemm_mma<128, 0>, cudaFuncAttributeMaxDynamicSharedMemorySize, SMEM_GEMM);
    cudaFuncSetAttribute(gemm_mma<KP3, 0>, cudaFuncAttributeMaxDynamicSharedMemorySize, SMEM_GEMM);
    cudaFuncSetAttribute(gemm_mma<KP3, 2>, cudaFuncAttributeMaxDynamicSharedMemorySize, SMEM_GEMM);
    cudaFuncSetAttribute(knn_mma, cudaFuncAttributeMaxDynamicSharedMemorySize, SMEM_KNN);
    cudaFuncSetAttribute(edge_mma<32>, cudaFuncAttributeMaxDynamicSharedMemorySize, SMEM_EDGE);
    cudaFuncSetAttribute(edge_mma<64>, cudaFuncAttributeMaxDynamicSharedMemorySize, SMEM_EDGE);

    const int knn_blocks = BC * (PP / 256);   // 512

    // setup: final-MLP weights + edge-conv weights + K-pad zeroing
    padzero_kernel<<<NPTS / 256, 256>>>(xah, xal, yah, yal);
    wconv_kernel<<<(NP2 * KP3 + 255) / 256, 256>>>(mW1, 128, wh + 0 * NP2 * KP3, wl + 0 * NP2 * KP3);
    wconv_kernel<<<(NP2 * KP3 + 255) / 256, 256>>>(mW2, 264, wh + 1 * NP2 * KP3, wl + 1 * NP2 * KP3);
    wconv_kernel<<<(NP2 * KP3 + 255) / 256, 256>>>(mW3, 264, wh + 2 * NP2 * KP3, wl + 2 * NP2 * KP3);
    wedge1_kernel<<<(32 * 64 + 255) / 256, 256>>>(c2W1, 32, e1h, e1l);
    wedge2_kernel<<<(32 * 32 + 255) / 256, 256>>>(c2W2, 32, e2h, e2l);
    wedge1_kernel<<<(64 * 64 + 255) / 256, 256>>>(c3W1, 64, e1h + 4096, e1l + 4096);
    wedge2_kernel<<<(64 * 64 + 255) / 256, 256>>>(c3W2, 64, e2h + 4096, e2l + 4096);

    // conv1: d=1 -> c=32 (cols 0..31)
    knn1_kernel<<<knn_blocks, 256>>>(x, knn);
    edge_conv1_kernel<<<NPTS / 8, 256>>>(x, knn, c1W1, c1b1, c1W2, c1b2, fah, fal);
    // conv2: kNN on x1 (blocks 0..1) + HMMA edge conv -> cols 32..63
    sqnorm_kernel<<<NPTS / 256, 256>>>(fah, fal, 0, sq);
    knn_mma<<<BC * 16, 256, SMEM_KNN>>>(fah, fal, 0, sq, knn);
    edge_mma<32><<<NPTS * 4 / 128, 128, SMEM_EDGE>>>(fah, fal, 0, knn,
                                                     e1h, e1l, e2h, e2l,
                                                     c2b1, c2b2, 32, fah, fal);
    // conv3: kNN on x2 (blocks 2..3) + HMMA edge conv -> cols 64..127
    sqnorm_kernel<<<NPTS / 256, 256>>>(fah, fal, 2, sq);
    knn_mma<<<BC * 16, 256, SMEM_KNN>>>(fah, fal, 2, sq, knn);
    edge_mma<64><<<NPTS * 4 / 128, 128, SMEM_EDGE>>>(fah, fal, 2, knn,
                                                     e1h + 4096, e1l + 4096,
                                                     e2h + 4096, e2l + 4096,
                                                     c3b1, c3b2, 64, fah, fal);

    // final MLP via double-buffered HMMA GEMMs (GEMM3 fuses final layer)
    dim3 gg(NPTS / 128);
    gemm_mma<128, 0><<<gg, 512, SMEM_GEMM>>>(fah, fal, wh + 0 * NP2 * KP3, wl + 0 * NP2 * KP3,
                                             mb1, xah, xal, nullptr, nullptr, nullptr);
    gemm_mma<KP3, 0><<<gg, 512, SMEM_GEMM>>>(xah, xal, wh + 1 * NP2 * KP3, wl + 1 * NP2 * KP3,
                                             mb2, yah, yal, nullptr, nullptr, nullptr);
    gemm_mma<KP3, 2><<<gg, 512, SMEM_GEMM>>>(yah, yal, wh + 2 * NP2 * KP3, wl + 2 * NP2 * KP3,
                                             mb3, nullptr, nullptr, mW4, mb4, out);
}

// round 14
// speedup vs baseline: 1.0245x; 1.0245x over previous
#include <cuda_runtime.h>
#include <cuda_bf16.h>
#include <float.h>
#include <math.h>
#include <stdint.h>

// Problem constants
#define BC   128
#define PP   1024
#define NPTS (BC*PP)   // 131072
#define KNN  4
#define KP3  288       // K padded to 288 (9 chunks of 32); N padded to 272
#define NP2  272

typedef unsigned long long ull;

// ---------------------------------------------------------------------------
// Scratch (device globals; no allocation allowed)
__device__ float          g_f   [NPTS * 64];        // fp32 [x1|x2] for edge convs (stride 64)
__device__ float          g_sq  [NPTS];             // per-point squared norms
__device__ __nv_bfloat16  g_fa_h[NPTS * 128];       // bf16-hi concat feats, fragment-permuted
__device__ __nv_bfloat16  g_fa_l[NPTS * 128];
__device__ __nv_bfloat16  g_xa_h[NPTS * KP3];       // h1 split, fragment-permuted
__device__ __nv_bfloat16  g_xa_l[NPTS * KP3];
__device__ __nv_bfloat16  g_ya_h[NPTS * KP3];       // h2 split, fragment-permuted
__device__ __nv_bfloat16  g_ya_l[NPTS * KP3];
__device__ __nv_bfloat16  g_w_h [3][NP2 * KP3];     // transposed split final-MLP weights
__device__ __nv_bfloat16  g_w_l [3][NP2 * KP3];
__device__ int            g_knn [NPTS * KNN];

// ---------------------------------------------------------------------------
// Fragment-permuted element offset: within each 16-k block, granule
// ((k>>1)&3)^(r&3) holds elements (2q2, 2q2+1, 2q2+8, 2q2+9).
__device__ __forceinline__ long permoff(int r, int k, int stride) {
    int blk = k >> 4;
    int q2  = (k >> 1) & 3;
    int hi  = (k >> 3) & 1;
    int gr  = q2 ^ (r & 3);
    return (long)r * stride + blk * 16 + gr * 4 + hi * 2 + (k & 1);
}

// ---------------------------------------------------------------------------
// packed f32x2 helpers (for SIMT kernels)
__device__ __forceinline__ ull fma2(ull a, ull b, ull c) {
    ull d; asm("fma.rn.f32x2 %0, %1, %2, %3;" : "=l"(d) : "l"(a), "l"(b), "l"(c));
    return d;
}
__device__ __forceinline__ ull dup2(float x) {
    ull d; unsigned u = __float_as_uint(x);
    asm("mov.b64 %0, {%1, %1};" : "=l"(d) : "r"(u));
    return d;
}
__device__ __forceinline__ ull pack2(float lo, float hi) {
    ull d;
    asm("mov.b64 %0, {%1, %2};" : "=l"(d)
        : "r"(__float_as_uint(lo)), "r"(__float_as_uint(hi)));
    return d;
}
__device__ __forceinline__ float2 unpack2(ull v) {
    unsigned l, h;
    asm("mov.b64 {%0, %1}, %2;" : "=r"(l), "=r"(h) : "l"(v));
    return make_float2(__uint_as_float(l), __uint_as_float(h));
}
__device__ __forceinline__ void bsplit(float v, __nv_bfloat16& h, __nv_bfloat16& l) {
    h = __float2bfloat16(v);
    l = __float2bfloat16(v - __bfloat162float(h));
}

// bf16 HMMA m16n8k16
__device__ __forceinline__ void mma16816(float* c, const uint32_t* a,
                                         uint32_t b0, uint32_t b1) {
    asm volatile(
        "mma.sync.aligned.m16n8k16.row.col.f32.bf16.bf16.f32 "
        "{%0,%1,%2,%3}, {%4,%5,%6,%7}, {%8,%9}, {%0,%1,%2,%3};"
        : "+f"(c[0]), "+f"(c[1]), "+f"(c[2]), "+f"(c[3])
        : "r"(a[0]), "r"(a[1]), "r"(a[2]), "r"(a[3]), "r"(b0), "r"(b1));
}

__device__ __forceinline__ uint32_t smem_u32(const void* p) {
    uint32_t a;
    asm("{ .reg .u64 t; cvta.to.shared.u64 t, %1; cvt.u32.u64 %0, t; }"
        : "=r"(a) : "l"(p));
    return a;
}
__device__ __forceinline__ uint2 lds64(uint32_t addr) {
    uint2 v;
    asm volatile("ld.shared.v2.u32 {%0,%1}, [%2];" : "=r"(v.x), "=r"(v.y) : "r"(addr));
    return v;
}
__device__ __forceinline__ void cp16(uint32_t saddr, const void* gaddr) {
    asm volatile("cp.async.cg.shared.global [%0], [%1], 16;" :: "r"(saddr), "l"(gaddr));
}
#define CP_COMMIT() asm volatile("cp.async.commit_group;" ::: "memory")
#define CP_WAIT1()  asm volatile("cp.async.wait_group 1;" ::: "memory")
#define CP_WAIT0()  asm volatile("cp.async.wait_group 0;" ::: "memory")

// top-4 insertion ladder (strict <, earliest-seen wins ties)
__device__ __forceinline__ void lad4(float* bs, int* bi, float s, int id) {
    if (s < bs[3]) {
        if (s < bs[2]) {
            bs[3] = bs[2]; bi[3] = bi[2];
            if (s < bs[1]) {
                bs[2] = bs[1]; bi[2] = bi[1];
                if (s < bs[0]) { bs[1] = bs[0]; bi[1] = bi[0]; bs[0] = s; bi[0] = id; }
                else           { bs[1] = s; bi[1] = id; }
            } else { bs[2] = s; bi[2] = id; }
        } else { bs[3] = s; bi[3] = id; }
    }
}

// ---------------------------------------------------------------------------
// kNN for D=1 (exact fp32; input feature space)
__global__ void knn1_kernel(const float* __restrict__ feat, int* __restrict__ kn) {
    const int NT = 256;
    __shared__ float s[NT];
    int cloud = blockIdx.x / (PP / 256);
    int tile  = blockIdx.x % (PP / 256);
    int gi    = cloud * PP + tile * 256 + threadIdx.x;

    float f0 = feat[gi];
    float bd[4] = { FLT_MAX, FLT_MAX, FLT_MAX, FLT_MAX };
    int   bi[4] = { 0, 0, 0, 0 };

    for (int j0 = 0; j0 < PP; j0 += NT) {
        __syncthreads();
        s[threadIdx.x] = feat[cloud * PP + j0 + threadIdx.x];
        __syncthreads();
        for (int jj = 0; jj < NT; jj++) {
            float df = f0 - s[jj];
            lad4(bd, bi, df * df, cloud * PP + j0 + jj);
        }
    }
    kn[gi*4+0] = bi[0]; kn[gi*4+1] = bi[1]; kn[gi*4+2] = bi[2]; kn[gi*4+3] = bi[3];
}

// ---------------------------------------------------------------------------
// Squared norms from the bf16 hi/lo split.
__global__ void sqnorm_kernel(const __nv_bfloat16* __restrict__ Fh,
                              const __nv_bfloat16* __restrict__ Fl,
                              int kb0, float* __restrict__ sq) {
    int p = blockIdx.x * 256 + threadIdx.x;
    if (p >= NPTS) return;
    const __nv_bfloat16* ph = Fh + (long)p * 128 + kb0 * 16;
    const __nv_bfloat16* pl = Fl + (long)p * 128 + kb0 * 16;
    float s = 0.f;
#pragma unroll
    for (int i = 0; i < 32; i++) {
        float v = __bfloat162float(ph[i]) + __bfloat162float(pl[i]);
        s = fmaf(v, v, s);
    }
    sq[p] = s;
}

// ---------------------------------------------------------------------------
// Fused HMMA kNN, one CTA per cloud: the full cloud (1024 rows x 2 terms,
// 80B padded stride) is staged ONCE into smem; 16 query tiles of 64 run
// entirely from smem (queries are a subset of candidates). Scores
// sq_j - 2*dot_ij; per-thread top-4 ladders merged via smem per tile.
__global__ void __launch_bounds__(256, 1)
knn_mma(const __nv_bfloat16* __restrict__ Fh, const __nv_bfloat16* __restrict__ Fl,
        int kb0, const float* __restrict__ sq, int* __restrict__ kn) {
    extern __shared__ char smem[];
    const int BSTR   = 80;
    const int BTERM  = PP * BSTR;        // 81920
    const int OFF_B  = 0;                // 2*BTERM = 163840
    const int OFF_SQ = 163840;           // 4096
    const int OFF_MG = 167936;           // 32768 (per-tile merge)

    uint32_t sb = smem_u32(smem);
    int tid = threadIdx.x, wid = tid >> 5, lane = tid & 31;
    int cloud = blockIdx.x;
    int gc0   = cloud * PP;
    int wm = wid >> 2, wn = wid & 3;     // 2 m-warps x 4 n-warps
    int g  = lane >> 2, qi = lane & 3, q = qi * 2;

    // stage the whole cloud once: 2 terms x 1024 rows x 4 x 16B
    for (int idx = tid; idx < 8192; idx += 256) {
        int term = idx >> 12, rem = idx & 4095;
        int r = rem >> 2, c = rem & 3;
        const __nv_bfloat16* src =
            (term ? Fl : Fh) + (long)(gc0 + r) * 128 + (kb0 + (c >> 1)) * 16 + (c & 1) * 8;
        cp16(sb + OFF_B + term * BTERM + r * BSTR + c * 16, src);
    }
    // sq: 1024 floats
    if (tid < 256)
        cp16(sb + OFF_SQ + tid * 16, sq + gc0 + tid * 4);
    CP_COMMIT();
    CP_WAIT0();
    __syncthreads();

    const float* ssq = (const float*)(smem + OFF_SQ);
    const uint32_t frOff = (uint32_t)((qi ^ (g & 3)) << 3);
    float2* mg = (float2*)(smem + OFF_MG);

    for (int qt = 0; qt < 16; qt++) {
        float bs[4][4]; int bi[4][4];
#pragma unroll
        for (int a = 0; a < 4; a++)
#pragma unroll
            for (int b = 0; b < 4; b++) { bs[a][b] = FLT_MAX; bi[a][b] = 0; }

        for (int nc = 0; nc < 4; nc++) {
#pragma unroll
            for (int mt = 0; mt < 2; mt++) {
                float acc[8][4];
#pragma unroll
                for (int nt = 0; nt < 8; nt++)
#pragma unroll
                    for (int c = 0; c < 4; c++) acc[nt][c] = 0.0f;

#pragma unroll
                for (int s = 0; s < 2; s++) {
                    int arow = qt * 64 + wm * 32 + mt * 16 + g;
                    uint32_t ao = (uint32_t)(arow * BSTR + s * 32) + frOff;
                    uint2 aHlo = lds64(sb + OFF_B + ao);
                    uint2 aHhi = lds64(sb + OFF_B + ao + 8 * BSTR);
                    uint2 aLlo = lds64(sb + OFF_B + BTERM + ao);
                    uint2 aLhi = lds64(sb + OFF_B + BTERM + ao + 8 * BSTR);
                    uint32_t aH[4] = { aHlo.x, aHhi.x, aHlo.y, aHhi.y };
                    uint32_t aL[4] = { aLlo.x, aLhi.x, aLlo.y, aLhi.y };
#pragma unroll
                    for (int nt = 0; nt < 8; nt++) {
                        int n = nc * 256 + wn * 64 + nt * 8 + g;
                        uint32_t bo = (uint32_t)(n * BSTR + s * 32) + frOff;
                        uint2 bh = lds64(sb + OFF_B + bo);
                        uint2 bl = lds64(sb + OFF_B + BTERM + bo);
                        mma16816(acc[nt], aH, bh.x, bh.y);
                        mma16816(acc[nt], aH, bl.x, bl.y);
                        mma16816(acc[nt], aL, bh.x, bh.y);
                    }
                }
#pragma unroll
                for (int nt = 0; nt < 8; nt++) {
                    int col = nc * 256 + wn * 64 + nt * 8 + q;
                    float sj0 = ssq[col], sj1 = ssq[col + 1];
#pragma unroll
                    for (int h = 0; h < 2; h++) {
                        int li = mt * 2 + h;
                        lad4(bs[li], bi[li], sj0 - 2.0f * acc[nt][h*2+0], col);
                        lad4(bs[li], bi[li], sj1 - 2.0f * acc[nt][h*2+1], col + 1);
                    }
                }
            }
        }

        // merge: 16 partial lists per query row of this tile
        int src = wn * 4 + qi;
#pragma unroll
        for (int mt = 0; mt < 2; mt++)
#pragma unroll
            for (int h = 0; h < 2; h++) {
                int row = wm * 32 + mt * 16 + h * 8 + g;
                int li = mt * 2 + h;
#pragma unroll
                for (int k = 0; k < 4; k++)
                    mg[(row * 16 + src) * 4 + k] =
                        make_float2(bs[li][k], __int_as_float(bi[li][k]));
            }
        __syncthreads();
        if (tid < 64) {
            float fs[4] = { FLT_MAX, FLT_MAX, FLT_MAX, FLT_MAX };
            int   fi[4] = { 0, 0, 0, 0 };
            const float2* rowp = mg + tid * 64;
            for (int e = 0; e < 64; e++) {
                float2 p = rowp[(e + tid) & 63];
                lad4(fs, fi, p.x, __float_as_int(p.y));
            }
            int gpt = gc0 + qt * 64 + tid;
#pragma unroll
            for (int k = 0; k < 4; k++) kn[gpt * 4 + k] = gc0 + fi[k];
        }
        __syncthreads();
    }
}

// ---------------------------------------------------------------------------
// Edge conv D=1: warp-per-point. fp32 f (stride 64) + permuted bf16 split (cols 0..31).
__global__ void edge_conv1_kernel(const float* __restrict__ feat,
                                  const int* __restrict__ kn,
                                  const float* __restrict__ W1, const float* __restrict__ b1,
                                  const float* __restrict__ W2, const float* __restrict__ b2,
                                  float* __restrict__ fo,
                                  __nv_bfloat16* __restrict__ bqh,
                                  __nv_bfloat16* __restrict__ bql) {
    const int C = 32;
    __shared__ float sW1[2 * C];
    __shared__ float sW2[C * C];
    __shared__ float sb1[C], sb2[C];
    __shared__ float sh[8][C];

    int tid = threadIdx.x;
    for (int i = tid; i < 2 * C; i += 256) sW1[i] = W1[i];
    for (int i = tid; i < C * C; i += 256) sW2[i] = W2[i];
    if (tid < C) { sb1[tid] = b1[tid]; sb2[tid] = b2[tid]; }
    __syncthreads();

    int w = tid / 32, lane = tid % 32;
    int pt = blockIdx.x * 8 + w;
    float xi = feat[pt];

    float acc = -FLT_MAX;
#pragma unroll
    for (int k = 0; k < KNN; k++) {
        int j = kn[pt * 4 + k];
        float dj = feat[j] - xi;
        float hv = fmaf(xi, sW1[lane], fmaf(dj, sW1[C + lane], sb1[lane]));
        sh[w][lane] = fmaxf(hv, 0.f);
        __syncwarp();
        float ov = sb2[lane];
#pragma unroll
        for (int t = 0; t < C; t++) ov = fmaf(sh[w][t], sW2[t * C + lane], ov);
        acc = fmaxf(acc, ov);
        __syncwarp();
    }
    fo[(long)pt * 64 + lane] = acc;
    __nv_bfloat16 h, l; bsplit(acc, h, l);
    long o = permoff(pt, lane, 128);
    bqh[o] = h;
    bql[o] = l;
}

// ---------------------------------------------------------------------------
// Edge conv D=32: thread-per-point (S=1) or 2 threads/point (S=2).
// Permuted bf16 split written at feature columns [colbase, colbase+C).
template<int C, int S, bool WF32>
__global__ void __launch_bounds__(128, 3)
edge_conv32(const float* __restrict__ feat, int fstride,
            const int* __restrict__ kn,
            const float* __restrict__ W1, const float* __restrict__ b1,
            const float* __restrict__ W2, const float* __restrict__ b2,
            float* __restrict__ fo, int fostride, int colbase,
            __nv_bfloat16* __restrict__ bqh,
            __nv_bfloat16* __restrict__ bql) {
    constexpr int E  = 64;
    constexpr int CO = C / S;
    __shared__ float sW1T[C][E];
    __shared__ float sW2[C][C];
    __shared__ float sb1[C];

    int tid = threadIdx.x;
    for (int i = tid; i < E * C; i += 128) sW1T[i % C][i / C] = W1[i];
    for (int i = tid; i < C * C; i += 128) sW2[i / C][i % C] = W2[i];
    for (int i = tid; i < C;     i += 128) sb1[i] = b1[i];
    __syncthreads();

    int thr = blockIdx.x * 128 + tid;
    int pt  = thr / S;
    int off = (thr % S) * CO;

    const float* xi_ptr = feat + (long)pt * fstride;
    ull xip[16];
#pragma unroll
    for (int q = 0; q < 8; q++) {
        float4 v = *(const float4*)(xi_ptr + q * 4);
        xip[2*q]   = pack2(v.x, v.y);
        xip[2*q+1] = pack2(v.z, v.w);
    }
    ull m1 = dup2(-1.0f);

    float omax[CO];
#pragma unroll
    for (int c = 0; c < CO; c++) omax[c] = -FLT_MAX;

#pragma unroll
    for (int k = 0; k < KNN; k++) {
        int j = kn[pt * 4 + k];
        const float* xj_ptr = feat + (long)j * fstride;
        ull dfp[16];
#pragma unroll
        for (int q = 0; q < 8; q++) {
            float4 v = *(const float4*)(xj_ptr + q * 4);
            dfp[2*q]   = fma2(xip[2*q],   m1, pack2(v.x, v.y));
            dfp[2*q+1] = fma2(xip[2*q+1], m1, pack2(v.z, v.w));
        }
        ull oe[CO / 2];
#pragma unroll
        for (int c = 0; c < CO / 2; c++) oe[c] = 0;

        for (int t2 = 0; t2 < C; t2++) {
            const ull* wp = (const ull*)&sW1T[t2][0];
            ull h0 = 0, h1 = 0;
#pragma unroll
            for (int q = 0; q < 16; q += 2) {
                h0 = fma2(xip[q],   wp[q],   h0);
                h1 = fma2(xip[q+1], wp[q+1], h1);
            }
#pragma unroll
            for (int q = 0; q < 16; q += 2) {
                h0 = fma2(dfp[q],   wp[16 + q],   h0);
                h1 = fma2(dfp[q+1], wp[16 + q+1], h1);
            }
            float2 a = unpack2(h0), b = unpack2(h1);
            float hv = sb1[t2] + ((a.x + a.y) + (b.x + b.y));
            hv = fmaxf(hv, 0.0f);
            ull hv2 = dup2(hv);
            const ull* w2p = (const ull*)&sW2[t2][off];
#pragma unroll
            for (int c = 0; c < CO / 2; c++) oe[c] = fma2(hv2, w2p[c], oe[c]);
        }
#pragma unroll
        for (int c = 0; c < CO / 2; c++) {
            float2 p = unpack2(oe[c]);
            omax[2*c]   = fmaxf(omax[2*c],   p.x);
            omax[2*c+1] = fmaxf(omax[2*c+1], p.y);
        }
    }
#pragma unroll
    for (int c = 0; c < CO / 2; c++) {
        int col = off + 2 * c;
        float v0 = omax[2*c]   + b2[col];
        float v1 = omax[2*c+1] + b2[col + 1];
        if (WF32) {
            fo[(long)pt * fostride + col]     = v0;
            fo[(long)pt * fostride + col + 1] = v1;
        }
        __nv_bfloat16 h0, l0, h1, l1;
        bsplit(v0, h0, l0); bsplit(v1, h1, l1);
        uint32_t ph = ((uint32_t)__bfloat16_as_ushort(h1) << 16) | __bfloat16_as_ushort(h0);
        uint32_t pl = ((uint32_t)__bfloat16_as_ushort(l1) << 16) | __bfloat16_as_ushort(l0);
        long o = permoff(pt, colbase + col, 128);
        *(uint32_t*)(bqh + o) = ph;
        *(uint32_t*)(bql + o) = pl;
    }
}

// ---------------------------------------------------------------------------
// Weight transpose + split to permuted layout: W[K,264] -> [NP2][KP3]
__global__ void wconv_kernel(const float* __restrict__ W, int K,
                             __nv_bfloat16* __restrict__ th,
                             __nv_bfloat16* __restrict__ tl) {
    int idx = blockIdx.x * 256 + threadIdx.x;
    if (idx >= NP2 * KP3) return;
    int n = idx / KP3, k = idx % KP3;
    float v = (n < 264 && k < K) ? W[(long)k * 264 + n] : 0.0f;
    __nv_bfloat16 h, l; bsplit(v, h, l);
    long o = permoff(n, k, KP3);
    th[o] = h; tl[o] = l;
}

// Zero activation K-pad blocks [272,288)
__global__ void padzero_kernel(__nv_bfloat16* a, __nv_bfloat16* b,
                               __nv_bfloat16* c, __nv_bfloat16* d) {
    int row = blockIdx.x * 256 + threadIdx.x;
    if (row >= NPTS) return;
    uint4 z = make_uint4(0, 0, 0, 0);
    long o = (long)row * KP3 + 272;
    *(uint4*)(a + o) = z; *(uint4*)(a + o + 8) = z;
    *(uint4*)(b + o) = z; *(uint4*)(b + o + 8) = z;
    *(uint4*)(c + o) = z; *(uint4*)(c + o + 8) = z;
    *(uint4*)(d + o) = z; *(uint4*)(d + o + 8) = z;
}

// ---------------------------------------------------------------------------
// HMMA bf16-split GEMM, cp.async double-buffered, conflict-free fragment smem.
// EPI 0: permuted bf16-split out. EPI 2: fused 264->2 + log_softmax.
template<int KTOT, int EPI>
__global__ void __launch_bounds__(512, 1)
gemm_mma(const __nv_bfloat16* __restrict__ Ah, const __nv_bfloat16* __restrict__ Al,
         const __nv_bfloat16* __restrict__ Bh, const __nv_bfloat16* __restrict__ Bl,
         const float* __restrict__ bias,
         __nv_bfloat16* __restrict__ Oh, __nv_bfloat16* __restrict__ Ol,
         const float* __restrict__ W4, const float* __restrict__ b4,
         float* __restrict__ Out) {
    extern __shared__ char smem[];
    const int OFF_W4 = 1088, OFF_RED = 3264, OFF_A = 5312, OFF_B = 54464;
    const int ABUF = 24576, ATERM = 12288, BBUF = 52224, BTERM = 26112;

    uint32_t sb = smem_u32(smem);
    int tid = threadIdx.x, wid = tid >> 5, lane = tid & 31;
    int m0 = blockIdx.x * 128;
    int wm = wid & 7, wn = wid >> 3;
    int g  = lane >> 2;
    int qi = lane & 3;
    int q  = qi * 2;

    float* bias_s = (float*)smem;
    if (tid < NP2) bias_s[tid] = (tid < 264) ? bias[tid] : 0.0f;
    if (EPI == 2) {
        float* w4s = (float*)(smem + OFF_W4);
        for (int i = tid; i < 544; i += 512) w4s[i] = (i < 528) ? W4[i] : 0.0f;
    }

    float acc[17][4];
#pragma unroll
    for (int t = 0; t < 17; t++)
#pragma unroll
        for (int c = 0; c < 4; c++) acc[t][c] = 0.0f;

    constexpr int NCH = KTOT / 32;

    auto stage = [&](int buf, int k0) {
#pragma unroll
        for (int l = 0; l < 2; l++) {
            int idx = tid + l * 512;
            int term = idx >> 9, rem = idx & 511;
            int r = rem >> 2, c = rem & 3;
            const __nv_bfloat16* src =
                (term ? Al : Ah) + (long)(m0 + r) * KTOT + k0 + c * 8;
            cp16(sb + OFF_A + buf * ABUF + term * ATERM + r * 96 + c * 16, src);
        }
        for (int idx = tid; idx < 2176; idx += 512) {
            int term = idx >= 1088;
            int rem  = idx - term * 1088;
            int n = rem >> 2, c = rem & 3;
            const __nv_bfloat16* src =
                (term ? Bl : Bh) + (long)n * KP3 + k0 + c * 8;
            cp16(sb + OFF_B + buf * BBUF + term * BTERM + n * 96 + c * 16, src);
        }
    };

    stage(0, 0);
    CP_COMMIT();

    const uint32_t frOff = (uint32_t)((qi ^ (g & 3)) << 3);
    const int rb = wm * 16 + g;

    for (int ch = 0; ch < NCH; ch++) {
        if (ch + 1 < NCH) {
            stage((ch + 1) & 1, (ch + 1) * 32);
            CP_COMMIT();
            CP_WAIT1();
        } else {
            CP_WAIT0();
        }
        __syncthreads();
        int buf = ch & 1;
        uint32_t aBase = sb + OFF_A + buf * ABUF;
        uint32_t bBase = sb + OFF_B + buf * BBUF;

#pragma unroll
        for (int s = 0; s < 2; s++) {
            uint32_t ao = (uint32_t)(rb * 96 + s * 32) + frOff;
            uint2 aHlo = lds64(aBase + ao);
            uint2 aHhi = lds64(aBase + ao + 8 * 96);
            uint2 aLlo = lds64(aBase + ATERM + ao);
            uint2 aLhi = lds64(aBase + ATERM + ao + 8 * 96);
            uint32_t aH[4] = { aHlo.x, aHhi.x, aHlo.y, aHhi.y };
            uint32_t aL[4] = { aLlo.x, aLhi.x, aLlo.y, aLhi.y };
#pragma unroll
            for (int t = 0; t < 17; t++) {
                int n = wn * 136 + t * 8 + g;
                uint32_t bo = (uint32_t)(n * 96 + s * 32) + frOff;
                uint2 bh = lds64(bBase + bo);
                uint2 bl = lds64(bBase + BTERM + bo);
                mma16816(acc[t], aH, bh.x, bh.y);
                mma16816(acc[t], aH, bl.x, bl.y);
                mma16816(acc[t], aL, bh.x, bh.y);
            }
        }
        __syncthreads();
    }

    int row0 = m0 + wm * 16 + g;
    if (EPI == 0) {
#pragma unroll
        for (int t = 0; t < 17; t++) {
            int c0 = wn * 136 + t * 8 + q;
            float b0 = bias_s[c0], b1v = bias_s[c0 + 1];
            float v00 = fmaxf(acc[t][0] + b0, 0.f);
            float v01 = fmaxf(acc[t][1] + b1v, 0.f);
            float v10 = fmaxf(acc[t][2] + b0, 0.f);
            float v11 = fmaxf(acc[t][3] + b1v, 0.f);
            __nv_bfloat16 h0, l0, h1, l1;
            bsplit(v00, h0, l0); bsplit(v01, h1, l1);
            uint32_t ph = ((uint32_t)__bfloat16_as_ushort(h1) << 16) | __bfloat16_as_ushort(h0);
            uint32_t pl = ((uint32_t)__bfloat16_as_ushort(l1) << 16) | __bfloat16_as_ushort(l0);
            long o = permoff(row0, c0, KP3);
            *(uint32_t*)(Oh + o) = ph;
            *(uint32_t*)(Ol + o) = pl;
            bsplit(v10, h0, l0); bsplit(v11, h1, l1);
            ph = ((uint32_t)__bfloat16_as_ushort(h1) << 16) | __bfloat16_as_ushort(h0);
            pl = ((uint32_t)__bfloat16_as_ushort(l1) << 16) | __bfloat16_as_ushort(l0);
            long o2 = permoff(row0 + 8, c0, KP3);
            *(uint32_t*)(Oh + o2) = ph;
            *(uint32_t*)(Ol + o2) = pl;
        }
    } else {
        const float* w4s = (const float*)(smem + OFF_W4);
        float p00 = 0.f, p01 = 0.f, p10 = 0.f, p11 = 0.f;
#pragma unroll
        for (int t = 0; t < 17; t++) {
            int c0 = wn * 136 + t * 8 + q;
            float b0 = bias_s[c0], b1v = bias_s[c0 + 1];
            float v00 = fmaxf(acc[t][0] + b0, 0.f);
            float v01 = fmaxf(acc[t][1] + b1v, 0.f);
            float v10 = fmaxf(acc[t][2] + b0, 0.f);
            float v11 = fmaxf(acc[t][3] + b1v, 0.f);
            float w00 = w4s[c0 * 2],       w01 = w4s[c0 * 2 + 1];
            float w10 = w4s[(c0 + 1) * 2], w11 = w4s[(c0 + 1) * 2 + 1];
            p00 = fmaf(v00, w00, fmaf(v01, w10, p00));
            p01 = fmaf(v00, w01, fmaf(v01, w11, p01));
            p10 = fmaf(v10, w00, fmaf(v11, w10, p10));
            p11 = fmaf(v10, w01, fmaf(v11, w11, p11));
        }
#pragma unroll
        for (int o = 1; o < 4; o <<= 1) {
            p00 += __shfl_xor_sync(0xFFFFFFFFu, p00, o);
            p01 += __shfl_xor_sync(0xFFFFFFFFu, p01, o);
            p10 += __shfl_xor_sync(0xFFFFFFFFu, p10, o);
            p11 += __shfl_xor_sync(0xFFFFFFFFu, p11, o);
        }
        float* red = (float*)(smem + OFF_RED);
        if (qi == 0) {
            int r = wm * 16 + g;
            red[(wn * 128 + r) * 2 + 0]     = p00;
            red[(wn * 128 + r) * 2 + 1]     = p01;
            red[(wn * 128 + r + 8) * 2 + 0] = p10;
            red[(wn * 128 + r + 8) * 2 + 1] = p11;
        }
        __syncthreads();
        if (tid < 128) {
            float o0 = red[tid * 2 + 0] + red[(128 + tid) * 2 + 0] + b4[0];
            float o1 = red[tid * 2 + 1] + red[(128 + tid) * 2 + 1] + b4[1];
            float m = fmaxf(o0, o1);
            float lse = m + logf(expf(o0 - m) + expf(o1 - m));
            Out[(long)(m0 + tid) * 2 + 0] = o0 - lse;
            Out[(long)(m0 + tid) * 2 + 1] = o1 - lse;
        }
    }
}

// ---------------------------------------------------------------------------
extern "C" void kernel_launch(void* const* d_in, const int* in_sizes, int n_in,
                              void* d_out, int out_size) {
    const float* x    = (const float*)d_in[0];
    const float* c1W1 = (const float*)d_in[2];
    const float* c1b1 = (const float*)d_in[3];
    const float* c1W2 = (const float*)d_in[4];
    const float* c1b2 = (const float*)d_in[5];
    const float* c2W1 = (const float*)d_in[6];
    const float* c2b1 = (const float*)d_in[7];
    const float* c2W2 = (const float*)d_in[8];
    const float* c2b2 = (const float*)d_in[9];
    const float* c3W1 = (const float*)d_in[10];
    const float* c3b1 = (const float*)d_in[11];
    const float* c3W2 = (const float*)d_in[12];
    const float* c3b2 = (const float*)d_in[13];
    const float* mW1  = (const float*)d_in[14];
    const float* mb1  = (const float*)d_in[15];
    const float* mW2  = (const float*)d_in[16];
    const float* mb2  = (const float*)d_in[17];
    const float* mW3  = (const float*)d_in[18];
    const float* mb3  = (const float*)d_in[19];
    const float* mW4  = (const float*)d_in[20];
    const float* mb4  = (const float*)d_in[21];
    float* out = (float*)d_out;

    float *f, *sq; int* knn;
    __nv_bfloat16 *fah, *fal, *xah, *xal, *yah, *yal, *wh, *wl;
    cudaGetSymbolAddress((void**)&f,   g_f);
    cudaGetSymbolAddress((void**)&sq,  g_sq);
    cudaGetSymbolAddress((void**)&knn, g_knn);
    cudaGetSymbolAddress((void**)&fah, g_fa_h);
    cudaGetSymbolAddress((void**)&fal, g_fa_l);
    cudaGetSymbolAddress((void**)&xah, g_xa_h);
    cudaGetSymbolAddress((void**)&xal, g_xa_l);
    cudaGetSymbolAddress((void**)&yah, g_ya_h);
    cudaGetSymbolAddress((void**)&yal, g_ya_l);
    cudaGetSymbolAddress((void**)&wh,  g_w_h);
    cudaGetSymbolAddress((void**)&wl,  g_w_l);

    const int SMEM_GEMM = 158912;
    const int SMEM_KNN  = 200704;
    cudaFuncSetAttribute(gemm_mma<128, 0>, cudaFuncAttributeMaxDynamicSharedMemorySize, SMEM_GEMM);
    cudaFuncSetAttribute(gemm_mma<KP3, 0>, cudaFuncAttributeMaxDynamicSharedMemorySize, SMEM_GEMM);
    cudaFuncSetAttribute(gemm_mma<KP3, 2>, cudaFuncAttributeMaxDynamicSharedMemorySize, SMEM_GEMM);
    cudaFuncSetAttribute(knn_mma, cudaFuncAttributeMaxDynamicSharedMemorySize, SMEM_KNN);

    const int knn_blocks = BC * (PP / 256);   // 512

    // setup
    padzero_kernel<<<NPTS / 256, 256>>>(xah, xal, yah, yal);
    wconv_kernel<<<(NP2 * KP3 + 255) / 256, 256>>>(mW1, 128, wh + 0 * NP2 * KP3, wl + 0 * NP2 * KP3);
    wconv_kernel<<<(NP2 * KP3 + 255) / 256, 256>>>(mW2, 264, wh + 1 * NP2 * KP3, wl + 1 * NP2 * KP3);
    wconv_kernel<<<(NP2 * KP3 + 255) / 256, 256>>>(mW3, 264, wh + 2 * NP2 * KP3, wl + 2 * NP2 * KP3);

    // conv1: d=1 -> c=32 (cols 0..31)
    knn1_kernel<<<knn_blocks, 256>>>(x, knn);
    edge_conv1_kernel<<<NPTS / 8, 256>>>(x, knn, c1W1, c1b1, c1W2, c1b2, f, fah, fal);
    // conv2: kNN on x1 (blocks 0..1; whole cloud resident) + SIMT edge conv -> cols 32..63
    sqnorm_kernel<<<NPTS / 256, 256>>>(fah, fal, 0, sq);
    knn_mma<<<BC, 256, SMEM_KNN>>>(fah, fal, 0, sq, knn);
    edge_conv32<32, 1, true><<<NPTS / 128, 128>>>(f, 64, knn, c2W1, c2b1, c2W2, c2b2,
                                                  f + 32, 64, 32, fah, fal);
    // conv3: kNN on x2 (blocks 2..3) + SIMT edge conv -> cols 64..127
    sqnorm_kernel<<<NPTS / 256, 256>>>(fah, fal, 2, sq);
    knn_mma<<<BC, 256, SMEM_KNN>>>(fah, fal, 2, sq, knn);
    edge_conv32<64, 2, false><<<2 * NPTS / 128, 128>>>(f + 32, 64, knn, c3W1, c3b1, c3W2, c3b2,
                                                       nullptr, 0, 64, fah, fal);

    // final MLP via double-buffered HMMA GEMMs (GEMM3 fuses final layer)
    dim3 gg(NPTS / 128);
    gemm_mma<128, 0><<<gg, 512, SMEM_GEMM>>>(fah, fal, wh + 0 * NP2 * KP3, wl + 0 * NP2 * KP3,
                                             mb1, xah, xal, nullptr, nullptr, nullptr);
    gemm_mma<KP3, 0><<<gg, 512, SMEM_GEMM>>>(xah, xal, wh + 1 * NP2 * KP3, wl + 1 * NP2 * KP3,
                                             mb2, yah, yal, nullptr, nullptr, nullptr);
    gemm_mma<KP3, 2><<<gg, 512, SMEM_GEMM>>>(yah, yal, wh + 2 * NP2 * KP3, wl + 2 * NP2 * KP3,
                                             mb3, nullptr, nullptr, mW4, mb4, out);
}

// round 15
// speedup vs baseline: 1.1455x; 1.1181x over previous
#include <cuda_runtime.h>
#include <cuda_bf16.h>
#include <float.h>
#include <math.h>
#include <stdint.h>

// Problem constants
#define BC   128
#define PP   1024
#define NPTS (BC*PP)   // 131072
#define KNN  4
#define KP3  288       // K padded to 288 (9 chunks of 32); N padded to 272
#define NP2  272

typedef unsigned long long ull;

// ---------------------------------------------------------------------------
// Scratch (device globals; no allocation allowed)
__device__ float          g_f   [NPTS * 64];        // fp32 [x1|x2] for edge convs (stride 64)
__device__ float          g_sq  [NPTS];             // per-point squared norms
__device__ __nv_bfloat16  g_fa_h[NPTS * 128];       // bf16-hi concat feats, fragment-permuted
__device__ __nv_bfloat16  g_fa_l[NPTS * 128];
__device__ __nv_bfloat16  g_xa_h[NPTS * KP3];       // h1 split, fragment-permuted
__device__ __nv_bfloat16  g_xa_l[NPTS * KP3];
__device__ __nv_bfloat16  g_ya_h[NPTS * KP3];       // h2 split, fragment-permuted
__device__ __nv_bfloat16  g_ya_l[NPTS * KP3];
__device__ __nv_bfloat16  g_w_h [3][NP2 * KP3];     // transposed split final-MLP weights
__device__ __nv_bfloat16  g_w_l [3][NP2 * KP3];
__device__ int            g_knn [NPTS * KNN];

// ---------------------------------------------------------------------------
// Fragment-permuted element offset: within each 16-k block, granule
// ((k>>1)&3)^(r&3) holds elements (2q2, 2q2+1, 2q2+8, 2q2+9).
__device__ __forceinline__ long permoff(int r, int k, int stride) {
    int blk = k >> 4;
    int q2  = (k >> 1) & 3;
    int hi  = (k >> 3) & 1;
    int gr  = q2 ^ (r & 3);
    return (long)r * stride + blk * 16 + gr * 4 + hi * 2 + (k & 1);
}

// ---------------------------------------------------------------------------
// packed f32x2 helpers (for SIMT kernels)
__device__ __forceinline__ ull fma2(ull a, ull b, ull c) {
    ull d; asm("fma.rn.f32x2 %0, %1, %2, %3;" : "=l"(d) : "l"(a), "l"(b), "l"(c));
    return d;
}
__device__ __forceinline__ ull dup2(float x) {
    ull d; unsigned u = __float_as_uint(x);
    asm("mov.b64 %0, {%1, %1};" : "=l"(d) : "r"(u));
    return d;
}
__device__ __forceinline__ ull pack2(float lo, float hi) {
    ull d;
    asm("mov.b64 %0, {%1, %2};" : "=l"(d)
        : "r"(__float_as_uint(lo)), "r"(__float_as_uint(hi)));
    return d;
}
__device__ __forceinline__ float2 unpack2(ull v) {
    unsigned l, h;
    asm("mov.b64 {%0, %1}, %2;" : "=r"(l), "=r"(h) : "l"(v));
    return make_float2(__uint_as_float(l), __uint_as_float(h));
}
__device__ __forceinline__ void bsplit(float v, __nv_bfloat16& h, __nv_bfloat16& l) {
    h = __float2bfloat16(v);
    l = __float2bfloat16(v - __bfloat162float(h));
}

// bf16 HMMA m16n8k16
__device__ __forceinline__ void mma16816(float* c, const uint32_t* a,
                                         uint32_t b0, uint32_t b1) {
    asm volatile(
        "mma.sync.aligned.m16n8k16.row.col.f32.bf16.bf16.f32 "
        "{%0,%1,%2,%3}, {%4,%5,%6,%7}, {%8,%9}, {%0,%1,%2,%3};"
        : "+f"(c[0]), "+f"(c[1]), "+f"(c[2]), "+f"(c[3])
        : "r"(a[0]), "r"(a[1]), "r"(a[2]), "r"(a[3]), "r"(b0), "r"(b1));
}

__device__ __forceinline__ uint32_t smem_u32(const void* p) {
    uint32_t a;
    asm("{ .reg .u64 t; cvta.to.shared.u64 t, %1; cvt.u32.u64 %0, t; }"
        : "=r"(a) : "l"(p));
    return a;
}
__device__ __forceinline__ uint2 lds64(uint32_t addr) {
    uint2 v;
    asm volatile("ld.shared.v2.u32 {%0,%1}, [%2];" : "=r"(v.x), "=r"(v.y) : "r"(addr));
    return v;
}
__device__ __forceinline__ void cp16(uint32_t saddr, const void* gaddr) {
    asm volatile("cp.async.cg.shared.global [%0], [%1], 16;" :: "r"(saddr), "l"(gaddr));
}
#define CP_COMMIT() asm volatile("cp.async.commit_group;" ::: "memory")
#define CP_WAIT1()  asm volatile("cp.async.wait_group 1;" ::: "memory")
#define CP_WAIT0()  asm volatile("cp.async.wait_group 0;" ::: "memory")

// top-4 insertion ladder (strict <, earliest-seen wins ties)
__device__ __forceinline__ void lad4(float* bs, int* bi, float s, int id) {
    if (s < bs[3]) {
        if (s < bs[2]) {
            bs[3] = bs[2]; bi[3] = bi[2];
            if (s < bs[1]) {
                bs[2] = bs[1]; bi[2] = bi[1];
                if (s < bs[0]) { bs[1] = bs[0]; bi[1] = bi[0]; bs[0] = s; bi[0] = id; }
                else           { bs[1] = s; bi[1] = id; }
            } else { bs[2] = s; bi[2] = id; }
        } else { bs[3] = s; bi[3] = id; }
    }
}

// ---------------------------------------------------------------------------
// kNN for D=1 (exact fp32; input feature space)
__global__ void knn1_kernel(const float* __restrict__ feat, int* __restrict__ kn) {
    const int NT = 256;
    __shared__ float s[NT];
    int cloud = blockIdx.x / (PP / 256);
    int tile  = blockIdx.x % (PP / 256);
    int gi    = cloud * PP + tile * 256 + threadIdx.x;

    float f0 = feat[gi];
    float bd[4] = { FLT_MAX, FLT_MAX, FLT_MAX, FLT_MAX };
    int   bi[4] = { 0, 0, 0, 0 };

    for (int j0 = 0; j0 < PP; j0 += NT) {
        __syncthreads();
        s[threadIdx.x] = feat[cloud * PP + j0 + threadIdx.x];
        __syncthreads();
        for (int jj = 0; jj < NT; jj++) {
            float df = f0 - s[jj];
            lad4(bd, bi, df * df, cloud * PP + j0 + jj);
        }
    }
    kn[gi*4+0] = bi[0]; kn[gi*4+1] = bi[1]; kn[gi*4+2] = bi[2]; kn[gi*4+3] = bi[3];
}

// ---------------------------------------------------------------------------
// Squared norms from the bf16 hi/lo split.
__global__ void sqnorm_kernel(const __nv_bfloat16* __restrict__ Fh,
                              const __nv_bfloat16* __restrict__ Fl,
                              int kb0, float* __restrict__ sq) {
    int p = blockIdx.x * 256 + threadIdx.x;
    if (p >= NPTS) return;
    const __nv_bfloat16* ph = Fh + (long)p * 128 + kb0 * 16;
    const __nv_bfloat16* pl = Fl + (long)p * 128 + kb0 * 16;
    float s = 0.f;
#pragma unroll
    for (int i = 0; i < 32; i++) {
        float v = __bfloat162float(ph[i]) + __bfloat162float(pl[i]);
        s = fmaf(v, v, s);
    }
    sq[p] = s;
}

// ---------------------------------------------------------------------------
// Fused HMMA kNN (D=32): per CTA 64 queries x 1024 candidates of one cloud.
// (R12 configuration: 16 CTAs per cloud, 2 CTAs/SM.)
__global__ void __launch_bounds__(256, 2)
knn_mma(const __nv_bfloat16* __restrict__ Fh, const __nv_bfloat16* __restrict__ Fl,
        int kb0, const float* __restrict__ sq, int* __restrict__ kn) {
    extern __shared__ char smem[];
    const int OFF_A  = 0;
    const int OFF_B  = 12288;
    const int OFF_SQ = 61440;
    const int OFF_MG = 12288;
    const int ATERM  = 64 * 96;
    const int BTERM  = 256 * 96;

    uint32_t sb = smem_u32(smem);
    int tid = threadIdx.x, wid = tid >> 5, lane = tid & 31;
    int cloud = blockIdx.x >> 4;
    int qbase = (blockIdx.x & 15) * 64;
    int gq    = cloud * PP + qbase;
    int gc0   = cloud * PP;
    int wm = wid >> 2, wn = wid & 3;
    int g  = lane >> 2, qi = lane & 3, q = qi * 2;

    for (int idx = tid; idx < 512; idx += 256) {
        int term = idx >> 8, rem = idx & 255;
        int r = rem >> 2, c = rem & 3;
        const __nv_bfloat16* src =
            (term ? Fl : Fh) + (long)(gq + r) * 128 + (kb0 + (c >> 1)) * 16 + (c & 1) * 8;
        cp16(sb + OFF_A + term * ATERM + r * 96 + c * 16, src);
    }
    CP_COMMIT();

    float bs[4][4]; int bi[4][4];
#pragma unroll
    for (int a = 0; a < 4; a++)
#pragma unroll
        for (int b = 0; b < 4; b++) { bs[a][b] = FLT_MAX; bi[a][b] = 0; }

    const uint32_t frOff = (uint32_t)((qi ^ (g & 3)) << 3);

    for (int nc = 0; nc < 4; nc++) {
        int cb = nc * 256;
        __syncthreads();
        for (int idx = tid; idx < 2048; idx += 256) {
            int term = idx >> 10, rem = idx & 1023;
            int r = rem >> 2, c = rem & 3;
            const __nv_bfloat16* src =
                (term ? Fl : Fh) + (long)(gc0 + cb + r) * 128 + (kb0 + (c >> 1)) * 16 + (c & 1) * 8;
            cp16(sb + OFF_B + term * BTERM + r * 96 + c * 16, src);
        }
        if (tid < 64)
            cp16(sb + OFF_SQ + tid * 16, sq + gc0 + cb + tid * 4);
        CP_COMMIT();
        CP_WAIT0();
        __syncthreads();

        const float* ssq = (const float*)(smem + OFF_SQ);
#pragma unroll
        for (int mt = 0; mt < 2; mt++) {
            float acc[8][4];
#pragma unroll
            for (int nt = 0; nt < 8; nt++)
#pragma unroll
                for (int c = 0; c < 4; c++) acc[nt][c] = 0.0f;

#pragma unroll
            for (int s = 0; s < 2; s++) {
                uint32_t ao = (uint32_t)((wm * 32 + mt * 16 + g) * 96 + s * 32) + frOff;
                uint2 aHlo = lds64(sb + OFF_A + ao);
                uint2 aHhi = lds64(sb + OFF_A + ao + 8 * 96);
                uint2 aLlo = lds64(sb + OFF_A + ATERM + ao);
                uint2 aLhi = lds64(sb + OFF_A + ATERM + ao + 8 * 96);
                uint32_t aH[4] = { aHlo.x, aHhi.x, aHlo.y, aHhi.y };
                uint32_t aL[4] = { aLlo.x, aLhi.x, aLlo.y, aLhi.y };
#pragma unroll
                for (int nt = 0; nt < 8; nt++) {
                    int n = wn * 64 + nt * 8 + g;
                    uint32_t bo = (uint32_t)(n * 96 + s * 32) + frOff;
                    uint2 bh = lds64(sb + OFF_B + bo);
                    uint2 bl = lds64(sb + OFF_B + BTERM + bo);
                    mma16816(acc[nt], aH, bh.x, bh.y);
                    mma16816(acc[nt], aH, bl.x, bl.y);
                    mma16816(acc[nt], aL, bh.x, bh.y);
                }
            }
#pragma unroll
            for (int nt = 0; nt < 8; nt++) {
                int col = wn * 64 + nt * 8 + q;
                float sj0 = ssq[col], sj1 = ssq[col + 1];
#pragma unroll
                for (int h = 0; h < 2; h++) {
                    int li = mt * 2 + h;
                    lad4(bs[li], bi[li], sj0 - 2.0f * acc[nt][h*2+0], cb + col);
                    lad4(bs[li], bi[li], sj1 - 2.0f * acc[nt][h*2+1], cb + col + 1);
                }
            }
        }
    }

    __syncthreads();
    float2* mg = (float2*)(smem + OFF_MG);
    int src = wn * 4 + qi;
#pragma unroll
    for (int mt = 0; mt < 2; mt++)
#pragma unroll
        for (int h = 0; h < 2; h++) {
            int row = wm * 32 + mt * 16 + h * 8 + g;
            int li = mt * 2 + h;
#pragma unroll
            for (int k = 0; k < 4; k++)
                mg[(row * 16 + src) * 4 + k] =
                    make_float2(bs[li][k], __int_as_float(bi[li][k]));
        }
    __syncthreads();
    if (tid < 64) {
        float fs[4] = { FLT_MAX, FLT_MAX, FLT_MAX, FLT_MAX };
        int   fi[4] = { 0, 0, 0, 0 };
        const float2* rowp = mg + tid * 64;
        for (int e = 0; e < 64; e++) {
            float2 p = rowp[(e + tid) & 63];
            lad4(fs, fi, p.x, __float_as_int(p.y));
        }
        int gpt = gq + tid;
#pragma unroll
        for (int k = 0; k < 4; k++) kn[gpt * 4 + k] = gc0 + fi[k];
    }
}

// ---------------------------------------------------------------------------
// Edge conv D=1: warp-per-point. fp32 f (stride 64) + permuted bf16 split (cols 0..31).
__global__ void edge_conv1_kernel(const float* __restrict__ feat,
                                  const int* __restrict__ kn,
                                  const float* __restrict__ W1, const float* __restrict__ b1,
                                  const float* __restrict__ W2, const float* __restrict__ b2,
                                  float* __restrict__ fo,
                                  __nv_bfloat16* __restrict__ bqh,
                                  __nv_bfloat16* __restrict__ bql) {
    const int C = 32;
    __shared__ float sW1[2 * C];
    __shared__ float sW2[C * C];
    __shared__ float sb1[C], sb2[C];
    __shared__ float sh[8][C];

    int tid = threadIdx.x;
    for (int i = tid; i < 2 * C; i += 256) sW1[i] = W1[i];
    for (int i = tid; i < C * C; i += 256) sW2[i] = W2[i];
    if (tid < C) { sb1[tid] = b1[tid]; sb2[tid] = b2[tid]; }
    __syncthreads();

    int w = tid / 32, lane = tid % 32;
    int pt = blockIdx.x * 8 + w;
    float xi = feat[pt];

    float acc = -FLT_MAX;
#pragma unroll
    for (int k = 0; k < KNN; k++) {
        int j = kn[pt * 4 + k];
        float dj = feat[j] - xi;
        float hv = fmaf(xi, sW1[lane], fmaf(dj, sW1[C + lane], sb1[lane]));
        sh[w][lane] = fmaxf(hv, 0.f);
        __syncwarp();
        float ov = sb2[lane];
#pragma unroll
        for (int t = 0; t < C; t++) ov = fmaf(sh[w][t], sW2[t * C + lane], ov);
        acc = fmaxf(acc, ov);
        __syncwarp();
    }
    fo[(long)pt * 64 + lane] = acc;
    __nv_bfloat16 h, l; bsplit(acc, h, l);
    long o = permoff(pt, lane, 128);
    bqh[o] = h;
    bql[o] = l;
}

// ---------------------------------------------------------------------------
// Edge conv D=32, C=32: thread-per-point (R12 configuration).
__global__ void __launch_bounds__(128)
edge_conv32s(const float* __restrict__ feat, int fstride,
             const int* __restrict__ kn,
             const float* __restrict__ W1, const float* __restrict__ b1,
             const float* __restrict__ W2, const float* __restrict__ b2,
             float* __restrict__ fo, int fostride, int colbase,
             __nv_bfloat16* __restrict__ bqh,
             __nv_bfloat16* __restrict__ bql) {
    const int C = 32, E = 64;
    __shared__ float sW1T[C][E];
    __shared__ float sW2[C][C];
    __shared__ float sb1[C];

    int tid = threadIdx.x;
    for (int i = tid; i < E * C; i += 128) sW1T[i % C][i / C] = W1[i];
    for (int i = tid; i < C * C; i += 128) sW2[i / C][i % C] = W2[i];
    for (int i = tid; i < C;     i += 128) sb1[i] = b1[i];
    __syncthreads();

    int pt = blockIdx.x * 128 + tid;

    const float* xi_ptr = feat + (long)pt * fstride;
    ull xip[16];
#pragma unroll
    for (int q = 0; q < 8; q++) {
        float4 v = *(const float4*)(xi_ptr + q * 4);
        xip[2*q]   = pack2(v.x, v.y);
        xip[2*q+1] = pack2(v.z, v.w);
    }
    ull m1 = dup2(-1.0f);

    float omax[C];
#pragma unroll
    for (int c = 0; c < C; c++) omax[c] = -FLT_MAX;

#pragma unroll
    for (int k = 0; k < KNN; k++) {
        int j = kn[pt * 4 + k];
        const float* xj_ptr = feat + (long)j * fstride;
        ull dfp[16];
#pragma unroll
        for (int q = 0; q < 8; q++) {
            float4 v = *(const float4*)(xj_ptr + q * 4);
            dfp[2*q]   = fma2(xip[2*q],   m1, pack2(v.x, v.y));
            dfp[2*q+1] = fma2(xip[2*q+1], m1, pack2(v.z, v.w));
        }
        ull oe[C / 2];
#pragma unroll
        for (int c = 0; c < C / 2; c++) oe[c] = 0;

        for (int t2 = 0; t2 < C; t2++) {
            const ull* wp = (const ull*)&sW1T[t2][0];
            ull h0 = 0, h1 = 0;
#pragma unroll
            for (int q = 0; q < 16; q += 2) {
                h0 = fma2(xip[q],   wp[q],   h0);
                h1 = fma2(xip[q+1], wp[q+1], h1);
            }
#pragma unroll
            for (int q = 0; q < 16; q += 2) {
                h0 = fma2(dfp[q],   wp[16 + q],   h0);
                h1 = fma2(dfp[q+1], wp[16 + q+1], h1);
            }
            float2 a = unpack2(h0), b = unpack2(h1);
            float hv = sb1[t2] + ((a.x + a.y) + (b.x + b.y));
            hv = fmaxf(hv, 0.0f);
            ull hv2 = dup2(hv);
            const ull* w2p = (const ull*)&sW2[t2][0];
#pragma unroll
            for (int c = 0; c < C / 2; c++) oe[c] = fma2(hv2, w2p[c], oe[c]);
        }
#pragma unroll
        for (int c = 0; c < C / 2; c++) {
            float2 p = unpack2(oe[c]);
            omax[2*c]   = fmaxf(omax[2*c],   p.x);
            omax[2*c+1] = fmaxf(omax[2*c+1], p.y);
        }
    }
#pragma unroll
    for (int c = 0; c < C / 2; c++) {
        int col = 2 * c;
        float v0 = omax[col]     + b2[col];
        float v1 = omax[col + 1] + b2[col + 1];
        fo[(long)pt * fostride + col]     = v0;
        fo[(long)pt * fostride + col + 1] = v1;
        __nv_bfloat16 h0, l0, h1, l1;
        bsplit(v0, h0, l0); bsplit(v1, h1, l1);
        uint32_t ph = ((uint32_t)__bfloat16_as_ushort(h1) << 16) | __bfloat16_as_ushort(h0);
        uint32_t pl = ((uint32_t)__bfloat16_as_ushort(l1) << 16) | __bfloat16_as_ushort(l0);
        long o = permoff(pt, colbase + col, 128);
        *(uint32_t*)(bqh + o) = ph;
        *(uint32_t*)(bql + o) = pl;
    }
}

// ---------------------------------------------------------------------------
// Edge conv D=32, C=64: HIDDEN-split — thread pair (adjacent lanes, same pt)
// each computes half the hidden units but layer-2 partials for ALL 64 outputs;
// pair exchanges partials via shfl, each thread max-reduces its 32-output half.
// Eliminates the layer-1 duplication of the old output-split (-33% work).
__global__ void __launch_bounds__(128)
edge_conv64h(const float* __restrict__ feat, int fstride,
             const int* __restrict__ kn,
             const float* __restrict__ W1, const float* __restrict__ b1,
             const float* __restrict__ W2, const float* __restrict__ b2,
             int colbase,
             __nv_bfloat16* __restrict__ bqh,
             __nv_bfloat16* __restrict__ bql) {
    const int C = 64, E = 64;
    __shared__ float sW1T[C][E];    // [t2][t]
    __shared__ float sW2[C][C];     // [t2][out]
    __shared__ float sb1[C];

    int tid = threadIdx.x;
    for (int i = tid; i < E * C; i += 128) sW1T[i % C][i / C] = W1[i];
    for (int i = tid; i < C * C; i += 128) sW2[i / C][i % C] = W2[i];
    for (int i = tid; i < C;     i += 128) sb1[i] = b1[i];
    __syncthreads();

    int thr = blockIdx.x * 128 + tid;
    int pt  = thr >> 1;
    int th  = thr & 1;              // hidden half (and output half)
    int t2b = th * 32;

    const float* xi_ptr = feat + (long)pt * fstride;
    ull xip[16];
#pragma unroll
    for (int q = 0; q < 8; q++) {
        float4 v = *(const float4*)(xi_ptr + q * 4);
        xip[2*q]   = pack2(v.x, v.y);
        xip[2*q+1] = pack2(v.z, v.w);
    }
    ull m1 = dup2(-1.0f);

    float omax[32];                 // my output half [th*32, th*32+32)
#pragma unroll
    for (int c = 0; c < 32; c++) omax[c] = -FLT_MAX;

    const unsigned FULL = 0xffffffffu;

#pragma unroll
    for (int k = 0; k < KNN; k++) {
        int j = kn[pt * 4 + k];
        const float* xj_ptr = feat + (long)j * fstride;
        ull dfp[16];
#pragma unroll
        for (int q = 0; q < 8; q++) {
            float4 v = *(const float4*)(xj_ptr + q * 4);
            dfp[2*q]   = fma2(xip[2*q],   m1, pack2(v.x, v.y));
            dfp[2*q+1] = fma2(xip[2*q+1], m1, pack2(v.z, v.w));
        }
        ull oe[32];                 // partial layer-2 sums, ALL 64 outputs
#pragma unroll
        for (int c = 0; c < 32; c++) oe[c] = 0;

        for (int t2i = 0; t2i < 32; t2i++) {
            int t2 = t2b + t2i;
            const ull* wp = (const ull*)&sW1T[t2][0];
            ull h0 = 0, h1 = 0;
#pragma unroll
            for (int q = 0; q < 16; q += 2) {
                h0 = fma2(xip[q],   wp[q],   h0);
                h1 = fma2(xip[q+1], wp[q+1], h1);
            }
#pragma unroll
            for (int q = 0; q < 16; q += 2) {
                h0 = fma2(dfp[q],   wp[16 + q],   h0);
                h1 = fma2(dfp[q+1], wp[16 + q+1], h1);
            }
            float2 a = unpack2(h0), b = unpack2(h1);
            float hv = sb1[t2] + ((a.x + a.y) + (b.x + b.y));
            hv = fmaxf(hv, 0.0f);
            ull hv2 = dup2(hv);
            const ull* w2p = (const ull*)&sW2[t2][0];
#pragma unroll
            for (int c = 0; c < 32; c++) oe[c] = fma2(hv2, w2p[c], oe[c]);
        }
        // pair exchange: send partner's half, receive mine; combine + max
        int myb = th * 16;          // ull base of my output half
        int pbv = (th ^ 1) * 16;    // ull base of partner's half
#pragma unroll
        for (int i = 0; i < 16; i++) {
            ull send = oe[pbv + i];
            ull recv = __shfl_xor_sync(FULL, send, 1);
            float2 a = unpack2(oe[myb + i]);
            float2 b = unpack2(recv);
            omax[2*i]   = fmaxf(omax[2*i],   a.x + b.x);
            omax[2*i+1] = fmaxf(omax[2*i+1], a.y + b.y);
        }
    }

#pragma unroll
    for (int i = 0; i < 16; i++) {
        int col = th * 32 + 2 * i;
        float v0 = omax[2*i]   + b2[col];
        float v1 = omax[2*i+1] + b2[col + 1];
        __nv_bfloat16 h0, l0, h1, l1;
        bsplit(v0, h0, l0); bsplit(v1, h1, l1);
        uint32_t ph = ((uint32_t)__bfloat16_as_ushort(h1) << 16) | __bfloat16_as_ushort(h0);
        uint32_t pl = ((uint32_t)__bfloat16_as_ushort(l1) << 16) | __bfloat16_as_ushort(l0);
        long o = permoff(pt, colbase + col, 128);
        *(uint32_t*)(bqh + o) = ph;
        *(uint32_t*)(bql + o) = pl;
    }
}

// ---------------------------------------------------------------------------
// Weight transpose + split to permuted layout: W[K,264] -> [NP2][KP3]
__global__ void wconv_kernel(const float* __restrict__ W, int K,
                             __nv_bfloat16* __restrict__ th,
                             __nv_bfloat16* __restrict__ tl) {
    int idx = blockIdx.x * 256 + threadIdx.x;
    if (idx >= NP2 * KP3) return;
    int n = idx / KP3, k = idx % KP3;
    float v = (n < 264 && k < K) ? W[(long)k * 264 + n] : 0.0f;
    __nv_bfloat16 h, l; bsplit(v, h, l);
    long o = permoff(n, k, KP3);
    th[o] = h; tl[o] = l;
}

// Zero activation K-pad blocks [272,288)
__global__ void padzero_kernel(__nv_bfloat16* a, __nv_bfloat16* b,
                               __nv_bfloat16* c, __nv_bfloat16* d) {
    int row = blockIdx.x * 256 + threadIdx.x;
    if (row >= NPTS) return;
    uint4 z = make_uint4(0, 0, 0, 0);
    long o = (long)row * KP3 + 272;
    *(uint4*)(a + o) = z; *(uint4*)(a + o + 8) = z;
    *(uint4*)(b + o) = z; *(uint4*)(b + o + 8) = z;
    *(uint4*)(c + o) = z; *(uint4*)(c + o + 8) = z;
    *(uint4*)(d + o) = z; *(uint4*)(d + o + 8) = z;
}

// ---------------------------------------------------------------------------
// HMMA bf16-split GEMM, cp.async double-buffered, conflict-free fragment smem.
// EPI 0: permuted bf16-split out. EPI 2: fused 264->2 + log_softmax.
template<int KTOT, int EPI>
__global__ void __launch_bounds__(512, 1)
gemm_mma(const __nv_bfloat16* __restrict__ Ah, const __nv_bfloat16* __restrict__ Al,
         const __nv_bfloat16* __restrict__ Bh, const __nv_bfloat16* __restrict__ Bl,
         const float* __restrict__ bias,
         __nv_bfloat16* __restrict__ Oh, __nv_bfloat16* __restrict__ Ol,
         const float* __restrict__ W4, const float* __restrict__ b4,
         float* __restrict__ Out) {
    extern __shared__ char smem[];
    const int OFF_W4 = 1088, OFF_RED = 3264, OFF_A = 5312, OFF_B = 54464;
    const int ABUF = 24576, ATERM = 12288, BBUF = 52224, BTERM = 26112;

    uint32_t sb = smem_u32(smem);
    int tid = threadIdx.x, wid = tid >> 5, lane = tid & 31;
    int m0 = blockIdx.x * 128;
    int wm = wid & 7, wn = wid >> 3;
    int g  = lane >> 2;
    int qi = lane & 3;
    int q  = qi * 2;

    float* bias_s = (float*)smem;
    if (tid < NP2) bias_s[tid] = (tid < 264) ? bias[tid] : 0.0f;
    if (EPI == 2) {
        float* w4s = (float*)(smem + OFF_W4);
        for (int i = tid; i < 544; i += 512) w4s[i] = (i < 528) ? W4[i] : 0.0f;
    }

    float acc[17][4];
#pragma unroll
    for (int t = 0; t < 17; t++)
#pragma unroll
        for (int c = 0; c < 4; c++) acc[t][c] = 0.0f;

    constexpr int NCH = KTOT / 32;

    auto stage = [&](int buf, int k0) {
#pragma unroll
        for (int l = 0; l < 2; l++) {
            int idx = tid + l * 512;
            int term = idx >> 9, rem = idx & 511;
            int r = rem >> 2, c = rem & 3;
            const __nv_bfloat16* src =
                (term ? Al : Ah) + (long)(m0 + r) * KTOT + k0 + c * 8;
            cp16(sb + OFF_A + buf * ABUF + term * ATERM + r * 96 + c * 16, src);
        }
        for (int idx = tid; idx < 2176; idx += 512) {
            int term = idx >= 1088;
            int rem  = idx - term * 1088;
            int n = rem >> 2, c = rem & 3;
            const __nv_bfloat16* src =
                (term ? Bl : Bh) + (long)n * KP3 + k0 + c * 8;
            cp16(sb + OFF_B + buf * BBUF + term * BTERM + n * 96 + c * 16, src);
        }
    };

    stage(0, 0);
    CP_COMMIT();

    const uint32_t frOff = (uint32_t)((qi ^ (g & 3)) << 3);
    const int rb = wm * 16 + g;

    for (int ch = 0; ch < NCH; ch++) {
        if (ch + 1 < NCH) {
            stage((ch + 1) & 1, (ch + 1) * 32);
            CP_COMMIT();
            CP_WAIT1();
        } else {
            CP_WAIT0();
        }
        __syncthreads();
        int buf = ch & 1;
        uint32_t aBase = sb + OFF_A + buf * ABUF;
        uint32_t bBase = sb + OFF_B + buf * BBUF;

#pragma unroll
        for (int s = 0; s < 2; s++) {
            uint32_t ao = (uint32_t)(rb * 96 + s * 32) + frOff;
            uint2 aHlo = lds64(aBase + ao);
            uint2 aHhi = lds64(aBase + ao + 8 * 96);
            uint2 aLlo = lds64(aBase + ATERM + ao);
            uint2 aLhi = lds64(aBase + ATERM + ao + 8 * 96);
            uint32_t aH[4] = { aHlo.x, aHhi.x, aHlo.y, aHhi.y };
            uint32_t aL[4] = { aLlo.x, aLhi.x, aLlo.y, aLhi.y };
#pragma unroll
            for (int t = 0; t < 17; t++) {
                int n = wn * 136 + t * 8 + g;
                uint32_t bo = (uint32_t)(n * 96 + s * 32) + frOff;
                uint2 bh = lds64(bBase + bo);
                uint2 bl = lds64(bBase + BTERM + bo);
                mma16816(acc[t], aH, bh.x, bh.y);
                mma16816(acc[t], aH, bl.x, bl.y);
                mma16816(acc[t], aL, bh.x, bh.y);
            }
        }
        __syncthreads();
    }

    int row0 = m0 + wm * 16 + g;
    if (EPI == 0) {
#pragma unroll
        for (int t = 0; t < 17; t++) {
            int c0 = wn * 136 + t * 8 + q;
            float b0 = bias_s[c0], b1v = bias_s[c0 + 1];
            float v00 = fmaxf(acc[t][0] + b0, 0.f);
            float v01 = fmaxf(acc[t][1] + b1v, 0.f);
            float v10 = fmaxf(acc[t][2] + b0, 0.f);
            float v11 = fmaxf(acc[t][3] + b1v, 0.f);
            __nv_bfloat16 h0, l0, h1, l1;
            bsplit(v00, h0, l0); bsplit(v01, h1, l1);
            uint32_t ph = ((uint32_t)__bfloat16_as_ushort(h1) << 16) | __bfloat16_as_ushort(h0);
            uint32_t pl = ((uint32_t)__bfloat16_as_ushort(l1) << 16) | __bfloat16_as_ushort(l0);
            long o = permoff(row0, c0, KP3);
            *(uint32_t*)(Oh + o) = ph;
            *(uint32_t*)(Ol + o) = pl;
            bsplit(v10, h0, l0); bsplit(v11, h1, l1);
            ph = ((uint32_t)__bfloat16_as_ushort(h1) << 16) | __bfloat16_as_ushort(h0);
            pl = ((uint32_t)__bfloat16_as_ushort(l1) << 16) | __bfloat16_as_ushort(l0);
            long o2 = permoff(row0 + 8, c0, KP3);
            *(uint32_t*)(Oh + o2) = ph;
            *(uint32_t*)(Ol + o2) = pl;
        }
    } else {
        const float* w4s = (const float*)(smem + OFF_W4);
        float p00 = 0.f, p01 = 0.f, p10 = 0.f, p11 = 0.f;
#pragma unroll
        for (int t = 0; t < 17; t++) {
            int c0 = wn * 136 + t * 8 + q;
            float b0 = bias_s[c0], b1v = bias_s[c0 + 1];
            float v00 = fmaxf(acc[t][0] + b0, 0.f);
            float v01 = fmaxf(acc[t][1] + b1v, 0.f);
            float v10 = fmaxf(acc[t][2] + b0, 0.f);
            float v11 = fmaxf(acc[t][3] + b1v, 0.f);
            float w00 = w4s[c0 * 2],       w01 = w4s[c0 * 2 + 1];
            float w10 = w4s[(c0 + 1) * 2], w11 = w4s[(c0 + 1) * 2 + 1];
            p00 = fmaf(v00, w00, fmaf(v01, w10, p00));
            p01 = fmaf(v00, w01, fmaf(v01, w11, p01));
            p10 = fmaf(v10, w00, fmaf(v11, w10, p10));
            p11 = fmaf(v10, w01, fmaf(v11, w11, p11));
        }
#pragma unroll
        for (int o = 1; o < 4; o <<= 1) {
            p00 += __shfl_xor_sync(0xFFFFFFFFu, p00, o);
            p01 += __shfl_xor_sync(0xFFFFFFFFu, p01, o);
            p10 += __shfl_xor_sync(0xFFFFFFFFu, p10, o);
            p11 += __shfl_xor_sync(0xFFFFFFFFu, p11, o);
        }
        float* red = (float*)(smem + OFF_RED);
        if (qi == 0) {
            int r = wm * 16 + g;
            red[(wn * 128 + r) * 2 + 0]     = p00;
            red[(wn * 128 + r) * 2 + 1]     = p01;
            red[(wn * 128 + r + 8) * 2 + 0] = p10;
            red[(wn * 128 + r + 8) * 2 + 1] = p11;
        }
        __syncthreads();
        if (tid < 128) {
            float o0 = red[tid * 2 + 0] + red[(128 + tid) * 2 + 0] + b4[0];
            float o1 = red[tid * 2 + 1] + red[(128 + tid) * 2 + 1] + b4[1];
            float m = fmaxf(o0, o1);
            float lse = m + logf(expf(o0 - m) + expf(o1 - m));
            Out[(long)(m0 + tid) * 2 + 0] = o0 - lse;
            Out[(long)(m0 + tid) * 2 + 1] = o1 - lse;
        }
    }
}

// ---------------------------------------------------------------------------
extern "C" void kernel_launch(void* const* d_in, const int* in_sizes, int n_in,
                              void* d_out, int out_size) {
    const float* x    = (const float*)d_in[0];
    const float* c1W1 = (const float*)d_in[2];
    const float* c1b1 = (const float*)d_in[3];
    const float* c1W2 = (const float*)d_in[4];
    const float* c1b2 = (const float*)d_in[5];
    const float* c2W1 = (const float*)d_in[6];
    const float* c2b1 = (const float*)d_in[7];
    const float* c2W2 = (const float*)d_in[8];
    const float* c2b2 = (const float*)d_in[9];
    const float* c3W1 = (const float*)d_in[10];
    const float* c3b1 = (const float*)d_in[11];
    const float* c3W2 = (const float*)d_in[12];
    const float* c3b2 = (const float*)d_in[13];
    const float* mW1  = (const float*)d_in[14];
    const float* mb1  = (const float*)d_in[15];
    const float* mW2  = (const float*)d_in[16];
    const float* mb2  = (const float*)d_in[17];
    const float* mW3  = (const float*)d_in[18];
    const float* mb3  = (const float*)d_in[19];
    const float* mW4  = (const float*)d_in[20];
    const float* mb4  = (const float*)d_in[21];
    float* out = (float*)d_out;

    float *f, *sq; int* knn;
    __nv_bfloat16 *fah, *fal, *xah, *xal, *yah, *yal, *wh, *wl;
    cudaGetSymbolAddress((void**)&f,   g_f);
    cudaGetSymbolAddress((void**)&sq,  g_sq);
    cudaGetSymbolAddress((void**)&knn, g_knn);
    cudaGetSymbolAddress((void**)&fah, g_fa_h);
    cudaGetSymbolAddress((void**)&fal, g_fa_l);
    cudaGetSymbolAddress((void**)&xah, g_xa_h);
    cudaGetSymbolAddress((void**)&xal, g_xa_l);
    cudaGetSymbolAddress((void**)&yah, g_ya_h);
    cudaGetSymbolAddress((void**)&yal, g_ya_l);
    cudaGetSymbolAddress((void**)&wh,  g_w_h);
    cudaGetSymbolAddress((void**)&wl,  g_w_l);

    const int SMEM_GEMM = 158912;
    const int SMEM_KNN  = 62464;
    cudaFuncSetAttribute(gemm_mma<128, 0>, cudaFuncAttributeMaxDynamicSharedMemorySize, SMEM_GEMM);
    cudaFuncSetAttribute(gemm_mma<KP3, 0>, cudaFuncAttributeMaxDynamicSharedMemorySize, SMEM_GEMM);
    cudaFuncSetAttribute(gemm_mma<KP3, 2>, cudaFuncAttributeMaxDynamicSharedMemorySize, SMEM_GEMM);
    cudaFuncSetAttribute(knn_mma, cudaFuncAttributeMaxDynamicSharedMemorySize, SMEM_KNN);

    const int knn_blocks = BC * (PP / 256);   // 512

    // setup
    padzero_kernel<<<NPTS / 256, 256>>>(xah, xal, yah, yal);
    wconv_kernel<<<(NP2 * KP3 + 255) / 256, 256>>>(mW1, 128, wh + 0 * NP2 * KP3, wl + 0 * NP2 * KP3);
    wconv_kernel<<<(NP2 * KP3 + 255) / 256, 256>>>(mW2, 264, wh + 1 * NP2 * KP3, wl + 1 * NP2 * KP3);
    wconv_kernel<<<(NP2 * KP3 + 255) / 256, 256>>>(mW3, 264, wh + 2 * NP2 * KP3, wl + 2 * NP2 * KP3);

    // conv1: d=1 -> c=32 (cols 0..31)
    knn1_kernel<<<knn_blocks, 256>>>(x, knn);
    edge_conv1_kernel<<<NPTS / 8, 256>>>(x, knn, c1W1, c1b1, c1W2, c1b2, f, fah, fal);
    // conv2: kNN on x1 (k-blocks 0..1) + SIMT edge conv -> cols 32..63
    sqnorm_kernel<<<NPTS / 256, 256>>>(fah, fal, 0, sq);
    knn_mma<<<BC * 16, 256, SMEM_KNN>>>(fah, fal, 0, sq, knn);
    edge_conv32s<<<NPTS / 128, 128>>>(f, 64, knn, c2W1, c2b1, c2W2, c2b2,
                                      f + 32, 64, 32, fah, fal);
    // conv3: kNN on x2 (k-blocks 2..3) + hidden-split edge conv -> cols 64..127
    sqnorm_kernel<<<NPTS / 256, 256>>>(fah, fal, 2, sq);
    knn_mma<<<BC * 16, 256, SMEM_KNN>>>(fah, fal, 2, sq, knn);
    edge_conv64h<<<2 * NPTS / 128, 128>>>(f + 32, 64, knn, c3W1, c3b1, c3W2, c3b2,
                                          64, fah, fal);

    // final MLP via double-buffered HMMA GEMMs (GEMM3 fuses final layer)
    dim3 gg(NPTS / 128);
    gemm_mma<128, 0><<<gg, 512, SMEM_GEMM>>>(fah, fal, wh + 0 * NP2 * KP3, wl + 0 * NP2 * KP3,
                                             mb1, xah, xal, nullptr, nullptr, nullptr);
    gemm_mma<KP3, 0><<<gg, 512, SMEM_GEMM>>>(xah, xal, wh + 1 * NP2 * KP3, wl + 1 * NP2 * KP3,
                                             mb2, yah, yal, nullptr, nullptr, nullptr);
    gemm_mma<KP3, 2><<<gg, 512, SMEM_GEMM>>>(yah, yal, wh + 2 * NP2 * KP3, wl + 2 * NP2 * KP3,
                                             mb3, nullptr, nullptr, mW4, mb4, out);
}

// round 16
// speedup vs baseline: 1.1539x; 1.0073x over previous
#include <cuda_runtime.h>
#include <cuda_bf16.h>
#include <float.h>
#include <math.h>
#include <stdint.h>

// Problem constants
#define BC   128
#define PP   1024
#define NPTS (BC*PP)   // 131072
#define KNN  4
#define KP3  288       // K padded to 288 (9 chunks of 32); N padded to 272
#define NP2  272

typedef unsigned long long ull;

// ---------------------------------------------------------------------------
// Scratch (device globals; no allocation allowed)
__device__ float          g_f   [NPTS * 64];        // fp32 [x1|x2] for edge convs (stride 64)
__device__ float          g_sq  [NPTS];             // per-point squared norms
__device__ __nv_bfloat16  g_fa_h[NPTS * 128];       // bf16-hi concat feats, fragment-permuted
__device__ __nv_bfloat16  g_fa_l[NPTS * 128];
__device__ __nv_bfloat16  g_xa_h[NPTS * KP3];       // h1 split, fragment-permuted
__device__ __nv_bfloat16  g_xa_l[NPTS * KP3];
__device__ __nv_bfloat16  g_ya_h[NPTS * KP3];       // h2 split, fragment-permuted
__device__ __nv_bfloat16  g_ya_l[NPTS * KP3];
__device__ __nv_bfloat16  g_w_h [3][NP2 * KP3];     // transposed split final-MLP weights
__device__ __nv_bfloat16  g_w_l [3][NP2 * KP3];
__device__ int            g_knn [NPTS * KNN];

// ---------------------------------------------------------------------------
// Fragment-permuted element offset: within each 16-k block, granule
// ((k>>1)&3)^(r&3) holds elements (2q2, 2q2+1, 2q2+8, 2q2+9).
__device__ __forceinline__ long permoff(int r, int k, int stride) {
    int blk = k >> 4;
    int q2  = (k >> 1) & 3;
    int hi  = (k >> 3) & 1;
    int gr  = q2 ^ (r & 3);
    return (long)r * stride + blk * 16 + gr * 4 + hi * 2 + (k & 1);
}

// ---------------------------------------------------------------------------
// packed f32x2 helpers (for SIMT kernels)
__device__ __forceinline__ ull fma2(ull a, ull b, ull c) {
    ull d; asm("fma.rn.f32x2 %0, %1, %2, %3;" : "=l"(d) : "l"(a), "l"(b), "l"(c));
    return d;
}
__device__ __forceinline__ ull dup2(float x) {
    ull d; unsigned u = __float_as_uint(x);
    asm("mov.b64 %0, {%1, %1};" : "=l"(d) : "r"(u));
    return d;
}
__device__ __forceinline__ ull pack2(float lo, float hi) {
    ull d;
    asm("mov.b64 %0, {%1, %2};" : "=l"(d)
        : "r"(__float_as_uint(lo)), "r"(__float_as_uint(hi)));
    return d;
}
__device__ __forceinline__ float2 unpack2(ull v) {
    unsigned l, h;
    asm("mov.b64 {%0, %1}, %2;" : "=r"(l), "=r"(h) : "l"(v));
    return make_float2(__uint_as_float(l), __uint_as_float(h));
}
__device__ __forceinline__ void bsplit(float v, __nv_bfloat16& h, __nv_bfloat16& l) {
    h = __float2bfloat16(v);
    l = __float2bfloat16(v - __bfloat162float(h));
}

// bf16 HMMA m16n8k16
__device__ __forceinline__ void mma16816(float* c, const uint32_t* a,
                                         uint32_t b0, uint32_t b1) {
    asm volatile(
        "mma.sync.aligned.m16n8k16.row.col.f32.bf16.bf16.f32 "
        "{%0,%1,%2,%3}, {%4,%5,%6,%7}, {%8,%9}, {%0,%1,%2,%3};"
        : "+f"(c[0]), "+f"(c[1]), "+f"(c[2]), "+f"(c[3])
        : "r"(a[0]), "r"(a[1]), "r"(a[2]), "r"(a[3]), "r"(b0), "r"(b1));
}

__device__ __forceinline__ uint32_t smem_u32(const void* p) {
    uint32_t a;
    asm("{ .reg .u64 t; cvta.to.shared.u64 t, %1; cvt.u32.u64 %0, t; }"
        : "=r"(a) : "l"(p));
    return a;
}
__device__ __forceinline__ uint2 lds64(uint32_t addr) {
    uint2 v;
    asm volatile("ld.shared.v2.u32 {%0,%1}, [%2];" : "=r"(v.x), "=r"(v.y) : "r"(addr));
    return v;
}
__device__ __forceinline__ void cp16(uint32_t saddr, const void* gaddr) {
    asm volatile("cp.async.cg.shared.global [%0], [%1], 16;" :: "r"(saddr), "l"(gaddr));
}
#define CP_COMMIT() asm volatile("cp.async.commit_group;" ::: "memory")
#define CP_WAIT1()  asm volatile("cp.async.wait_group 1;" ::: "memory")
#define CP_WAIT0()  asm volatile("cp.async.wait_group 0;" ::: "memory")

// top-4 insertion ladder (strict <, earliest-seen wins ties)
__device__ __forceinline__ void lad4(float* bs, int* bi, float s, int id) {
    if (s < bs[3]) {
        if (s < bs[2]) {
            bs[3] = bs[2]; bi[3] = bi[2];
            if (s < bs[1]) {
                bs[2] = bs[1]; bi[2] = bi[1];
                if (s < bs[0]) { bs[1] = bs[0]; bi[1] = bi[0]; bs[0] = s; bi[0] = id; }
                else           { bs[1] = s; bi[1] = id; }
            } else { bs[2] = s; bi[2] = id; }
        } else { bs[3] = s; bi[3] = id; }
    }
}

// ---------------------------------------------------------------------------
// kNN for D=1 (exact fp32; input feature space)
__global__ void knn1_kernel(const float* __restrict__ feat, int* __restrict__ kn) {
    const int NT = 256;
    __shared__ float s[NT];
    int cloud = blockIdx.x / (PP / 256);
    int tile  = blockIdx.x % (PP / 256);
    int gi    = cloud * PP + tile * 256 + threadIdx.x;

    float f0 = feat[gi];
    float bd[4] = { FLT_MAX, FLT_MAX, FLT_MAX, FLT_MAX };
    int   bi[4] = { 0, 0, 0, 0 };

    for (int j0 = 0; j0 < PP; j0 += NT) {
        __syncthreads();
        s[threadIdx.x] = feat[cloud * PP + j0 + threadIdx.x];
        __syncthreads();
        for (int jj = 0; jj < NT; jj++) {
            float df = f0 - s[jj];
            lad4(bd, bi, df * df, cloud * PP + j0 + jj);
        }
    }
    kn[gi*4+0] = bi[0]; kn[gi*4+1] = bi[1]; kn[gi*4+2] = bi[2]; kn[gi*4+3] = bi[3];
}

// ---------------------------------------------------------------------------
// Squared norms from the bf16 hi/lo split.
__global__ void sqnorm_kernel(const __nv_bfloat16* __restrict__ Fh,
                              const __nv_bfloat16* __restrict__ Fl,
                              int kb0, float* __restrict__ sq) {
    int p = blockIdx.x * 256 + threadIdx.x;
    if (p >= NPTS) return;
    const __nv_bfloat16* ph = Fh + (long)p * 128 + kb0 * 16;
    const __nv_bfloat16* pl = Fl + (long)p * 128 + kb0 * 16;
    float s = 0.f;
#pragma unroll
    for (int i = 0; i < 32; i++) {
        float v = __bfloat162float(ph[i]) + __bfloat162float(pl[i]);
        s = fmaf(v, v, s);
    }
    sq[p] = s;
}

// ---------------------------------------------------------------------------
// Fused HMMA kNN (D=32): per CTA 64 queries x 1024 candidates of one cloud.
// (R12 configuration: 16 CTAs per cloud, 2 CTAs/SM.)
__global__ void __launch_bounds__(256, 2)
knn_mma(const __nv_bfloat16* __restrict__ Fh, const __nv_bfloat16* __restrict__ Fl,
        int kb0, const float* __restrict__ sq, int* __restrict__ kn) {
    extern __shared__ char smem[];
    const int OFF_A  = 0;
    const int OFF_B  = 12288;
    const int OFF_SQ = 61440;
    const int OFF_MG = 12288;
    const int ATERM  = 64 * 96;
    const int BTERM  = 256 * 96;

    uint32_t sb = smem_u32(smem);
    int tid = threadIdx.x, wid = tid >> 5, lane = tid & 31;
    int cloud = blockIdx.x >> 4;
    int qbase = (blockIdx.x & 15) * 64;
    int gq    = cloud * PP + qbase;
    int gc0   = cloud * PP;
    int wm = wid >> 2, wn = wid & 3;
    int g  = lane >> 2, qi = lane & 3, q = qi * 2;

    for (int idx = tid; idx < 512; idx += 256) {
        int term = idx >> 8, rem = idx & 255;
        int r = rem >> 2, c = rem & 3;
        const __nv_bfloat16* src =
            (term ? Fl : Fh) + (long)(gq + r) * 128 + (kb0 + (c >> 1)) * 16 + (c & 1) * 8;
        cp16(sb + OFF_A + term * ATERM + r * 96 + c * 16, src);
    }
    CP_COMMIT();

    float bs[4][4]; int bi[4][4];
#pragma unroll
    for (int a = 0; a < 4; a++)
#pragma unroll
        for (int b = 0; b < 4; b++) { bs[a][b] = FLT_MAX; bi[a][b] = 0; }

    const uint32_t frOff = (uint32_t)((qi ^ (g & 3)) << 3);

    for (int nc = 0; nc < 4; nc++) {
        int cb = nc * 256;
        __syncthreads();
        for (int idx = tid; idx < 2048; idx += 256) {
            int term = idx >> 10, rem = idx & 1023;
            int r = rem >> 2, c = rem & 3;
            const __nv_bfloat16* src =
                (term ? Fl : Fh) + (long)(gc0 + cb + r) * 128 + (kb0 + (c >> 1)) * 16 + (c & 1) * 8;
            cp16(sb + OFF_B + term * BTERM + r * 96 + c * 16, src);
        }
        if (tid < 64)
            cp16(sb + OFF_SQ + tid * 16, sq + gc0 + cb + tid * 4);
        CP_COMMIT();
        CP_WAIT0();
        __syncthreads();

        const float* ssq = (const float*)(smem + OFF_SQ);
#pragma unroll
        for (int mt = 0; mt < 2; mt++) {
            float acc[8][4];
#pragma unroll
            for (int nt = 0; nt < 8; nt++)
#pragma unroll
                for (int c = 0; c < 4; c++) acc[nt][c] = 0.0f;

#pragma unroll
            for (int s = 0; s < 2; s++) {
                uint32_t ao = (uint32_t)((wm * 32 + mt * 16 + g) * 96 + s * 32) + frOff;
                uint2 aHlo = lds64(sb + OFF_A + ao);
                uint2 aHhi = lds64(sb + OFF_A + ao + 8 * 96);
                uint2 aLlo = lds64(sb + OFF_A + ATERM + ao);
                uint2 aLhi = lds64(sb + OFF_A + ATERM + ao + 8 * 96);
                uint32_t aH[4] = { aHlo.x, aHhi.x, aHlo.y, aHhi.y };
                uint32_t aL[4] = { aLlo.x, aLhi.x, aLlo.y, aLhi.y };
#pragma unroll
                for (int nt = 0; nt < 8; nt++) {
                    int n = wn * 64 + nt * 8 + g;
                    uint32_t bo = (uint32_t)(n * 96 + s * 32) + frOff;
                    uint2 bh = lds64(sb + OFF_B + bo);
                    uint2 bl = lds64(sb + OFF_B + BTERM + bo);
                    mma16816(acc[nt], aH, bh.x, bh.y);
                    mma16816(acc[nt], aH, bl.x, bl.y);
                    mma16816(acc[nt], aL, bh.x, bh.y);
                }
            }
#pragma unroll
            for (int nt = 0; nt < 8; nt++) {
                int col = wn * 64 + nt * 8 + q;
                float sj0 = ssq[col], sj1 = ssq[col + 1];
#pragma unroll
                for (int h = 0; h < 2; h++) {
                    int li = mt * 2 + h;
                    lad4(bs[li], bi[li], sj0 - 2.0f * acc[nt][h*2+0], cb + col);
                    lad4(bs[li], bi[li], sj1 - 2.0f * acc[nt][h*2+1], cb + col + 1);
                }
            }
        }
    }

    __syncthreads();
    float2* mg = (float2*)(smem + OFF_MG);
    int src = wn * 4 + qi;
#pragma unroll
    for (int mt = 0; mt < 2; mt++)
#pragma unroll
        for (int h = 0; h < 2; h++) {
            int row = wm * 32 + mt * 16 + h * 8 + g;
            int li = mt * 2 + h;
#pragma unroll
            for (int k = 0; k < 4; k++)
                mg[(row * 16 + src) * 4 + k] =
                    make_float2(bs[li][k], __int_as_float(bi[li][k]));
        }
    __syncthreads();
    if (tid < 64) {
        float fs[4] = { FLT_MAX, FLT_MAX, FLT_MAX, FLT_MAX };
        int   fi[4] = { 0, 0, 0, 0 };
        const float2* rowp = mg + tid * 64;
        for (int e = 0; e < 64; e++) {
            float2 p = rowp[(e + tid) & 63];
            lad4(fs, fi, p.x, __float_as_int(p.y));
        }
        int gpt = gq + tid;
#pragma unroll
        for (int k = 0; k < 4; k++) kn[gpt * 4 + k] = gc0 + fi[k];
    }
}

// ---------------------------------------------------------------------------
// Edge conv D=1: warp-per-point. fp32 f (stride 64) + permuted bf16 split (cols 0..31).
__global__ void edge_conv1_kernel(const float* __restrict__ feat,
                                  const int* __restrict__ kn,
                                  const float* __restrict__ W1, const float* __restrict__ b1,
                                  const float* __restrict__ W2, const float* __restrict__ b2,
                                  float* __restrict__ fo,
                                  __nv_bfloat16* __restrict__ bqh,
                                  __nv_bfloat16* __restrict__ bql) {
    const int C = 32;
    __shared__ float sW1[2 * C];
    __shared__ float sW2[C * C];
    __shared__ float sb1[C], sb2[C];
    __shared__ float sh[8][C];

    int tid = threadIdx.x;
    for (int i = tid; i < 2 * C; i += 256) sW1[i] = W1[i];
    for (int i = tid; i < C * C; i += 256) sW2[i] = W2[i];
    if (tid < C) { sb1[tid] = b1[tid]; sb2[tid] = b2[tid]; }
    __syncthreads();

    int w = tid / 32, lane = tid % 32;
    int pt = blockIdx.x * 8 + w;
    float xi = feat[pt];

    float acc = -FLT_MAX;
#pragma unroll
    for (int k = 0; k < KNN; k++) {
        int j = kn[pt * 4 + k];
        float dj = feat[j] - xi;
        float hv = fmaf(xi, sW1[lane], fmaf(dj, sW1[C + lane], sb1[lane]));
        sh[w][lane] = fmaxf(hv, 0.f);
        __syncwarp();
        float ov = sb2[lane];
#pragma unroll
        for (int t = 0; t < C; t++) ov = fmaf(sh[w][t], sW2[t * C + lane], ov);
        acc = fmaxf(acc, ov);
        __syncwarp();
    }
    fo[(long)pt * 64 + lane] = acc;
    __nv_bfloat16 h, l; bsplit(acc, h, l);
    long o = permoff(pt, lane, 128);
    bqh[o] = h;
    bql[o] = l;
}

// ---------------------------------------------------------------------------
// Edge conv D=32: thread-per-point (S=1) or 2 threads/point (S=2, output split).
// Permuted bf16 split written at feature columns [colbase, colbase+C).
// (R12 configuration.)
template<int C, int S, bool WF32>
__global__ void __launch_bounds__(128)
edge_conv32(const float* __restrict__ feat, int fstride,
            const int* __restrict__ kn,
            const float* __restrict__ W1, const float* __restrict__ b1,
            const float* __restrict__ W2, const float* __restrict__ b2,
            float* __restrict__ fo, int fostride, int colbase,
            __nv_bfloat16* __restrict__ bqh,
            __nv_bfloat16* __restrict__ bql) {
    constexpr int E  = 64;
    constexpr int CO = C / S;
    __shared__ float sW1T[C][E];
    __shared__ float sW2[C][C];
    __shared__ float sb1[C];

    int tid = threadIdx.x;
    for (int i = tid; i < E * C; i += 128) sW1T[i % C][i / C] = W1[i];
    for (int i = tid; i < C * C; i += 128) sW2[i / C][i % C] = W2[i];
    for (int i = tid; i < C;     i += 128) sb1[i] = b1[i];
    __syncthreads();

    int thr = blockIdx.x * 128 + tid;
    int pt  = thr / S;
    int off = (thr % S) * CO;

    const float* xi_ptr = feat + (long)pt * fstride;
    ull xip[16];
#pragma unroll
    for (int q = 0; q < 8; q++) {
        float4 v = *(const float4*)(xi_ptr + q * 4);
        xip[2*q]   = pack2(v.x, v.y);
        xip[2*q+1] = pack2(v.z, v.w);
    }
    ull m1 = dup2(-1.0f);

    float omax[CO];
#pragma unroll
    for (int c = 0; c < CO; c++) omax[c] = -FLT_MAX;

#pragma unroll
    for (int k = 0; k < KNN; k++) {
        int j = kn[pt * 4 + k];
        const float* xj_ptr = feat + (long)j * fstride;
        ull dfp[16];
#pragma unroll
        for (int q = 0; q < 8; q++) {
            float4 v = *(const float4*)(xj_ptr + q * 4);
            dfp[2*q]   = fma2(xip[2*q],   m1, pack2(v.x, v.y));
            dfp[2*q+1] = fma2(xip[2*q+1], m1, pack2(v.z, v.w));
        }
        ull oe[CO / 2];
#pragma unroll
        for (int c = 0; c < CO / 2; c++) oe[c] = 0;

        for (int t2 = 0; t2 < C; t2++) {
            const ull* wp = (const ull*)&sW1T[t2][0];
            ull h0 = 0, h1 = 0;
#pragma unroll
            for (int q = 0; q < 16; q += 2) {
                h0 = fma2(xip[q],   wp[q],   h0);
                h1 = fma2(xip[q+1], wp[q+1], h1);
            }
#pragma unroll
            for (int q = 0; q < 16; q += 2) {
                h0 = fma2(dfp[q],   wp[16 + q],   h0);
                h1 = fma2(dfp[q+1], wp[16 + q+1], h1);
            }
            float2 a = unpack2(h0), b = unpack2(h1);
            float hv = sb1[t2] + ((a.x + a.y) + (b.x + b.y));
            hv = fmaxf(hv, 0.0f);
            ull hv2 = dup2(hv);
            const ull* w2p = (const ull*)&sW2[t2][off];
#pragma unroll
            for (int c = 0; c < CO / 2; c++) oe[c] = fma2(hv2, w2p[c], oe[c]);
        }
#pragma unroll
        for (int c = 0; c < CO / 2; c++) {
            float2 p = unpack2(oe[c]);
            omax[2*c]   = fmaxf(omax[2*c],   p.x);
            omax[2*c+1] = fmaxf(omax[2*c+1], p.y);
        }
    }
#pragma unroll
    for (int c = 0; c < CO / 2; c++) {
        int col = off + 2 * c;
        float v0 = omax[2*c]   + b2[col];
        float v1 = omax[2*c+1] + b2[col + 1];
        if (WF32) {
            fo[(long)pt * fostride + col]     = v0;
            fo[(long)pt * fostride + col + 1] = v1;
        }
        __nv_bfloat16 h0, l0, h1, l1;
        bsplit(v0, h0, l0); bsplit(v1, h1, l1);
        uint32_t ph = ((uint32_t)__bfloat16_as_ushort(h1) << 16) | __bfloat16_as_ushort(h0);
        uint32_t pl = ((uint32_t)__bfloat16_as_ushort(l1) << 16) | __bfloat16_as_ushort(l0);
        long o = permoff(pt, colbase + col, 128);
        *(uint32_t*)(bqh + o) = ph;
        *(uint32_t*)(bql + o) = pl;
    }
}

// ---------------------------------------------------------------------------
// Weight transpose + split to permuted layout: W[K,264] -> [NP2][KP3]
__global__ void wconv_kernel(const float* __restrict__ W, int K,
                             __nv_bfloat16* __restrict__ th,
                             __nv_bfloat16* __restrict__ tl) {
    int idx = blockIdx.x * 256 + threadIdx.x;
    if (idx >= NP2 * KP3) return;
    int n = idx / KP3, k = idx % KP3;
    float v = (n < 264 && k < K) ? W[(long)k * 264 + n] : 0.0f;
    __nv_bfloat16 h, l; bsplit(v, h, l);
    long o = permoff(n, k, KP3);
    th[o] = h; tl[o] = l;
}

// Zero activation K-pad blocks [272,288)
__global__ void padzero_kernel(__nv_bfloat16* a, __nv_bfloat16* b,
                               __nv_bfloat16* c, __nv_bfloat16* d) {
    int row = blockIdx.x * 256 + threadIdx.x;
    if (row >= NPTS) return;
    uint4 z = make_uint4(0, 0, 0, 0);
    long o = (long)row * KP3 + 272;
    *(uint4*)(a + o) = z; *(uint4*)(a + o + 8) = z;
    *(uint4*)(b + o) = z; *(uint4*)(b + o + 8) = z;
    *(uint4*)(c + o) = z; *(uint4*)(c + o + 8) = z;
    *(uint4*)(d + o) = z; *(uint4*)(d + o + 8) = z;
}

// ---------------------------------------------------------------------------
// HMMA bf16-split GEMM, cp.async double-buffered, conflict-free fragment smem.
// EPI 0: permuted bf16-split out. EPI 2: fused 264->2 + log_softmax.
template<int KTOT, int EPI>
__global__ void __launch_bounds__(512, 1)
gemm_mma(const __nv_bfloat16* __restrict__ Ah, const __nv_bfloat16* __restrict__ Al,
         const __nv_bfloat16* __restrict__ Bh, const __nv_bfloat16* __restrict__ Bl,
         const float* __restrict__ bias,
         __nv_bfloat16* __restrict__ Oh, __nv_bfloat16* __restrict__ Ol,
         const float* __restrict__ W4, const float* __restrict__ b4,
         float* __restrict__ Out) {
    extern __shared__ char smem[];
    const int OFF_W4 = 1088, OFF_RED = 3264, OFF_A = 5312, OFF_B = 54464;
    const int ABUF = 24576, ATERM = 12288, BBUF = 52224, BTERM = 26112;

    uint32_t sb = smem_u32(smem);
    int tid = threadIdx.x, wid = tid >> 5, lane = tid & 31;
    int m0 = blockIdx.x * 128;
    int wm = wid & 7, wn = wid >> 3;
    int g  = lane >> 2;
    int qi = lane & 3;
    int q  = qi * 2;

    float* bias_s = (float*)smem;
    if (tid < NP2) bias_s[tid] = (tid < 264) ? bias[tid] : 0.0f;
    if (EPI == 2) {
        float* w4s = (float*)(smem + OFF_W4);
        for (int i = tid; i < 544; i += 512) w4s[i] = (i < 528) ? W4[i] : 0.0f;
    }

    float acc[17][4];
#pragma unroll
    for (int t = 0; t < 17; t++)
#pragma unroll
        for (int c = 0; c < 4; c++) acc[t][c] = 0.0f;

    constexpr int NCH = KTOT / 32;

    auto stage = [&](int buf, int k0) {
#pragma unroll
        for (int l = 0; l < 2; l++) {
            int idx = tid + l * 512;
            int term = idx >> 9, rem = idx & 511;
            int r = rem >> 2, c = rem & 3;
            const __nv_bfloat16* src =
                (term ? Al : Ah) + (long)(m0 + r) * KTOT + k0 + c * 8;
            cp16(sb + OFF_A + buf * ABUF + term * ATERM + r * 96 + c * 16, src);
        }
        for (int idx = tid; idx < 2176; idx += 512) {
            int term = idx >= 1088;
            int rem  = idx - term * 1088;
            int n = rem >> 2, c = rem & 3;
            const __nv_bfloat16* src =
                (term ? Bl : Bh) + (long)n * KP3 + k0 + c * 8;
            cp16(sb + OFF_B + buf * BBUF + term * BTERM + n * 96 + c * 16, src);
        }
    };

    stage(0, 0);
    CP_COMMIT();

    const uint32_t frOff = (uint32_t)((qi ^ (g & 3)) << 3);
    const int rb = wm * 16 + g;

    for (int ch = 0; ch < NCH; ch++) {
        if (ch + 1 < NCH) {
            stage((ch + 1) & 1, (ch + 1) * 32);
            CP_COMMIT();
            CP_WAIT1();
        } else {
            CP_WAIT0();
        }
        __syncthreads();
        int buf = ch & 1;
        uint32_t aBase = sb + OFF_A + buf * ABUF;
        uint32_t bBase = sb + OFF_B + buf * BBUF;

#pragma unroll
        for (int s = 0; s < 2; s++) {
            uint32_t ao = (uint32_t)(rb * 96 + s * 32) + frOff;
            uint2 aHlo = lds64(aBase + ao);
            uint2 aHhi = lds64(aBase + ao + 8 * 96);
            uint2 aLlo = lds64(aBase + ATERM + ao);
            uint2 aLhi = lds64(aBase + ATERM + ao + 8 * 96);
            uint32_t aH[4] = { aHlo.x, aHhi.x, aHlo.y, aHhi.y };
            uint32_t aL[4] = { aLlo.x, aLhi.x, aLlo.y, aLhi.y };
#pragma unroll
            for (int t = 0; t < 17; t++) {
                int n = wn * 136 + t * 8 + g;
                uint32_t bo = (uint32_t)(n * 96 + s * 32) + frOff;
                uint2 bh = lds64(bBase + bo);
                uint2 bl = lds64(bBase + BTERM + bo);
                mma16816(acc[t], aH, bh.x, bh.y);
                mma16816(acc[t], aH, bl.x, bl.y);
                mma16816(acc[t], aL, bh.x, bh.y);
            }
        }
        __syncthreads();
    }

    int row0 = m0 + wm * 16 + g;
    if (EPI == 0) {
#pragma unroll
        for (int t = 0; t < 17; t++) {
            int c0 = wn * 136 + t * 8 + q;
            float b0 = bias_s[c0], b1v = bias_s[c0 + 1];
            float v00 = fmaxf(acc[t][0] + b0, 0.f);
            float v01 = fmaxf(acc[t][1] + b1v, 0.f);
            float v10 = fmaxf(acc[t][2] + b0, 0.f);
            float v11 = fmaxf(acc[t][3] + b1v, 0.f);
            __nv_bfloat16 h0, l0, h1, l1;
            bsplit(v00, h0, l0); bsplit(v01, h1, l1);
            uint32_t ph = ((uint32_t)__bfloat16_as_ushort(h1) << 16) | __bfloat16_as_ushort(h0);
            uint32_t pl = ((uint32_t)__bfloat16_as_ushort(l1) << 16) | __bfloat16_as_ushort(l0);
            long o = permoff(row0, c0, KP3);
            *(uint32_t*)(Oh + o) = ph;
            *(uint32_t*)(Ol + o) = pl;
            bsplit(v10, h0, l0); bsplit(v11, h1, l1);
            ph = ((uint32_t)__bfloat16_as_ushort(h1) << 16) | __bfloat16_as_ushort(h0);
            pl = ((uint32_t)__bfloat16_as_ushort(l1) << 16) | __bfloat16_as_ushort(l0);
            long o2 = permoff(row0 + 8, c0, KP3);
            *(uint32_t*)(Oh + o2) = ph;
            *(uint32_t*)(Ol + o2) = pl;
        }
    } else {
        const float* w4s = (const float*)(smem + OFF_W4);
        float p00 = 0.f, p01 = 0.f, p10 = 0.f, p11 = 0.f;
#pragma unroll
        for (int t = 0; t < 17; t++) {
            int c0 = wn * 136 + t * 8 + q;
            float b0 = bias_s[c0], b1v = bias_s[c0 + 1];
            float v00 = fmaxf(acc[t][0] + b0, 0.f);
            float v01 = fmaxf(acc[t][1] + b1v, 0.f);
            float v10 = fmaxf(acc[t][2] + b0, 0.f);
            float v11 = fmaxf(acc[t][3] + b1v, 0.f);
            float w00 = w4s[c0 * 2],       w01 = w4s[c0 * 2 + 1];
            float w10 = w4s[(c0 + 1) * 2], w11 = w4s[(c0 + 1) * 2 + 1];
            p00 = fmaf(v00, w00, fmaf(v01, w10, p00));
            p01 = fmaf(v00, w01, fmaf(v01, w11, p01));
            p10 = fmaf(v10, w00, fmaf(v11, w10, p10));
            p11 = fmaf(v10, w01, fmaf(v11, w11, p11));
        }
#pragma unroll
        for (int o = 1; o < 4; o <<= 1) {
            p00 += __shfl_xor_sync(0xFFFFFFFFu, p00, o);
            p01 += __shfl_xor_sync(0xFFFFFFFFu, p01, o);
            p10 += __shfl_xor_sync(0xFFFFFFFFu, p10, o);
            p11 += __shfl_xor_sync(0xFFFFFFFFu, p11, o);
        }
        float* red = (float*)(smem + OFF_RED);
        if (qi == 0) {
            int r = wm * 16 + g;
            red[(wn * 128 + r) * 2 + 0]     = p00;
            red[(wn * 128 + r) * 2 + 1]     = p01;
            red[(wn * 128 + r + 8) * 2 + 0] = p10;
            red[(wn * 128 + r + 8) * 2 + 1] = p11;
        }
        __syncthreads();
        if (tid < 128) {
            float o0 = red[tid * 2 + 0] + red[(128 + tid) * 2 + 0] + b4[0];
            float o1 = red[tid * 2 + 1] + red[(128 + tid) * 2 + 1] + b4[1];
            float m = fmaxf(o0, o1);
            float lse = m + logf(expf(o0 - m) + expf(o1 - m));
            Out[(long)(m0 + tid) * 2 + 0] = o0 - lse;
            Out[(long)(m0 + tid) * 2 + 1] = o1 - lse;
        }
    }
}

// ---------------------------------------------------------------------------
extern "C" void kernel_launch(void* const* d_in, const int* in_sizes, int n_in,
                              void* d_out, int out_size) {
    const float* x    = (const float*)d_in[0];
    const float* c1W1 = (const float*)d_in[2];
    const float* c1b1 = (const float*)d_in[3];
    const float* c1W2 = (const float*)d_in[4];
    const float* c1b2 = (const float*)d_in[5];
    const float* c2W1 = (const float*)d_in[6];
    const float* c2b1 = (const float*)d_in[7];
    const float* c2W2 = (const float*)d_in[8];
    const float* c2b2 = (const float*)d_in[9];
    const float* c3W1 = (const float*)d_in[10];
    const float* c3b1 = (const float*)d_in[11];
    const float* c3W2 = (const float*)d_in[12];
    const float* c3b2 = (const float*)d_in[13];
    const float* mW1  = (const float*)d_in[14];
    const float* mb1  = (const float*)d_in[15];
    const float* mW2  = (const float*)d_in[16];
    const float* mb2  = (const float*)d_in[17];
    const float* mW3  = (const float*)d_in[18];
    const float* mb3  = (const float*)d_in[19];
    const float* mW4  = (const float*)d_in[20];
    const float* mb4  = (const float*)d_in[21];
    float* out = (float*)d_out;

    float *f, *sq; int* knn;
    __nv_bfloat16 *fah, *fal, *xah, *xal, *yah, *yal, *wh, *wl;
    cudaGetSymbolAddress((void**)&f,   g_f);
    cudaGetSymbolAddress((void**)&sq,  g_sq);
    cudaGetSymbolAddress((void**)&knn, g_knn);
    cudaGetSymbolAddress((void**)&fah, g_fa_h);
    cudaGetSymbolAddress((void**)&fal, g_fa_l);
    cudaGetSymbolAddress((void**)&xah, g_xa_h);
    cudaGetSymbolAddress((void**)&xal, g_xa_l);
    cudaGetSymbolAddress((void**)&yah, g_ya_h);
    cudaGetSymbolAddress((void**)&yal, g_ya_l);
    cudaGetSymbolAddress((void**)&wh,  g_w_h);
    cudaGetSymbolAddress((void**)&wl,  g_w_l);

    const int SMEM_GEMM = 158912;
    const int SMEM_KNN  = 62464;
    cudaFuncSetAttribute(gemm_mma<128, 0>, cudaFuncAttributeMaxDynamicSharedMemorySize, SMEM_GEMM);
    cudaFuncSetAttribute(gemm_mma<KP3, 0>, cudaFuncAttributeMaxDynamicSharedMemorySize, SMEM_GEMM);
    cudaFuncSetAttribute(gemm_mma<KP3, 2>, cudaFuncAttributeMaxDynamicSharedMemorySize, SMEM_GEMM);
    cudaFuncSetAttribute(knn_mma, cudaFuncAttributeMaxDynamicSharedMemorySize, SMEM_KNN);

    const int knn_blocks = BC * (PP / 256);   // 512

    // Launch order arranged so ncu's early-launch capture window lands on the
    // heavy unknowns: #4 = knn_mma, #6 = edge_conv32<32,1>.
    // (1) conv1 kNN
    knn1_kernel<<<knn_blocks, 256>>>(x, knn);
    // (2) conv1 edge conv -> cols 0..31
    edge_conv1_kernel<<<NPTS / 8, 256>>>(x, knn, c1W1, c1b1, c1W2, c1b2, f, fah, fal);
    // (3) sq norms on x1
    sqnorm_kernel<<<NPTS / 256, 256>>>(fah, fal, 0, sq);
    // (4) conv2 kNN (captured by ncu)
    knn_mma<<<BC * 16, 256, SMEM_KNN>>>(fah, fal, 0, sq, knn);
    // (5) pad zeroing (independent filler)
    padzero_kernel<<<NPTS / 256, 256>>>(xah, xal, yah, yal);
    // (6) conv2 edge conv -> cols 32..63 (alternate capture slot)
    edge_conv32<32, 1, true><<<NPTS / 128, 128>>>(f, 64, knn, c2W1, c2b1, c2W2, c2b2,
                                                  f + 32, 64, 32, fah, fal);
    // (7) sq norms on x2
    sqnorm_kernel<<<NPTS / 256, 256>>>(fah, fal, 2, sq);
    // (8) conv3 kNN
    knn_mma<<<BC * 16, 256, SMEM_KNN>>>(fah, fal, 2, sq, knn);
    // (9) conv3 edge conv -> cols 64..127
    edge_conv32<64, 2, false><<<2 * NPTS / 128, 128>>>(f + 32, 64, knn, c3W1, c3b1, c3W2, c3b2,
                                                       nullptr, 0, 64, fah, fal);
    // (10-12) final-MLP weight prep
    wconv_kernel<<<(NP2 * KP3 + 255) / 256, 256>>>(mW1, 128, wh + 0 * NP2 * KP3, wl + 0 * NP2 * KP3);
    wconv_kernel<<<(NP2 * KP3 + 255) / 256, 256>>>(mW2, 264, wh + 1 * NP2 * KP3, wl + 1 * NP2 * KP3);
    wconv_kernel<<<(NP2 * KP3 + 255) / 256, 256>>>(mW3, 264, wh + 2 * NP2 * KP3, wl + 2 * NP2 * KP3);

    // final MLP via double-buffered HMMA GEMMs (GEMM3 fuses final layer)
    dim3 gg(NPTS / 128);
    gemm_mma<128, 0><<<gg, 512, SMEM_GEMM>>>(fah, fal, wh + 0 * NP2 * KP3, wl + 0 * NP2 * KP3,
                                             mb1, xah, xal, nullptr, nullptr, nullptr);
    gemm_mma<KP3, 0><<<gg, 512, SMEM_GEMM>>>(xah, xal, wh + 1 * NP2 * KP3, wl + 1 * NP2 * KP3,
                                             mb2, yah, yal, nullptr, nullptr, nullptr);
    gemm_mma<KP3, 2><<<gg, 512, SMEM_GEMM>>>(yah, yal, wh + 2 * NP2 * KP3, wl + 2 * NP2 * KP3,
                                             mb3, nullptr, nullptr, mW4, mb4, out);
}